// round 10
// baseline (speedup 1.0000x reference)
#include <cuda_runtime.h>
#include <math.h>
#include <stdint.h>

#define B 8
#define C 512
#define N 1024
#define TOPK 12
#define NCHP 16
#define PC (C/NCHP)     // 32 channels per pred chunk
#define OC 8            // output c-blocks (C/64)

// ---------------- device scratch (no allocations allowed) ----------------
__device__ float    g_FP[B*C], g_BP[B*C];
__device__ float    g_predfg[B*N], g_predbg[B*N];
__device__ float    g_invn[B*N], g_qn[B*N];
__device__ float    g_wf[B*N];
__device__ float    g_wfsum[B];
__device__ int      g_idx[B*N];
__device__ int      g_M[B];
__device__ int      g_Mpad[B];
__device__ float    g_invg[B*N];
__device__ uint32_t g_qt[(size_t)B*C*N];     // q pre-converted to tf32 bits
__device__ uint32_t g_Vg[(size_t)B*C*N];     // gathered active columns, tf32 bits (zero-padded)
__device__ uint32_t g_S[(size_t)B*N*N];      // exp scores, tf32 bits (zero beyond Mb)
__device__ float    g_denom[B*N];
__device__ float    g_fgp[B*C], g_bgp[B*C];

// split partials
__device__ float g_pdf[NCHP][B*N], g_pdb[NCHP][B*N], g_pqq[NCHP][B*N];
__device__ float g_odf[OC][B*N], g_odb[OC][B*N], g_obb[OC][B*N];

// ---------------- helpers ----------------
__device__ __forceinline__ float warp_sum(float v) {
    #pragma unroll
    for (int off = 16; off > 0; off >>= 1) v += __shfl_down_sync(0xffffffffu, v, off);
    return v;
}

__device__ __forceinline__ uint32_t f2tf32(float f) {
    uint32_t u;
    asm("cvt.rna.tf32.f32 %0, %1;" : "=r"(u) : "f"(f));
    return u;
}

__device__ __forceinline__ void mma_tf32(float c[4],
                                         uint32_t a0, uint32_t a1, uint32_t a2, uint32_t a3,
                                         uint32_t b0, uint32_t b1) {
    asm volatile("mma.sync.aligned.m16n8k8.row.col.f32.tf32.tf32.f32 "
                 "{%0,%1,%2,%3}, {%4,%5,%6,%7}, {%8,%9}, {%0,%1,%2,%3};"
                 : "+f"(c[0]), "+f"(c[1]), "+f"(c[2]), "+f"(c[3])
                 : "r"(a0), "r"(a1), "r"(a2), "r"(a3), "r"(b0), "r"(b1));
}

// ---------------- K1: masked avg pool (FP/BP) + inline counts, one warp per (b,c) ----------------
__global__ void k_pool(const float* __restrict__ sf, const int* __restrict__ mask) {
    int w = blockIdx.x * 8 + (threadIdx.x >> 5);
    int lane = threadIdx.x & 31;
    int b = w / C, c = w % C;
    const float4* row4 = (const float4*)(sf + (size_t)w*N);
    const int4*   m4   = (const int4*)(mask + b*N);
    float s1 = 0.f, s0 = 0.f, c1 = 0.f;
    #pragma unroll
    for (int i = 0; i < 8; i++) {
        int p = lane + i*32;
        float4 v = row4[p];
        int4 mk = m4[p];
        float fx = (float)mk.x, fy = (float)mk.y, fz = (float)mk.z, fw = (float)mk.w;
        s1 += fx*v.x + fy*v.y + fz*v.z + fw*v.w;
        s0 += (1.f-fx)*v.x + (1.f-fy)*v.y + (1.f-fz)*v.z + (1.f-fw)*v.w;
        c1 += fx + fy + fz + fw;
    }
    s1 = warp_sum(s1); s0 = warp_sum(s0); c1 = warp_sum(c1);
    if (lane == 0) {
        g_FP[b*C + c] = s1 / (c1 + 1e-5f);
        g_BP[b*C + c] = s0 / ((float)N - c1 + 1e-5f);
    }
}

// ---------------- K2a: split-C partial dot products, 4 pixels/thread via float4 ----------------
__global__ __launch_bounds__(256) void k_pred1(const float* __restrict__ q) {
    int t = threadIdx.x;
    int g4 = blockIdx.x * 256 + t;          // pixel-quad id
    int chunk = blockIdx.y;
    int b = g4 >> 8;                        // 256 quads per batch
    int n = (g4 & 255) * 4;
    const float* qb = q + (size_t)b*C*N + (size_t)chunk*PC*N + n;
    const float* fp = g_FP + b*C + chunk*PC;
    const float* bp = g_BP + b*C + chunk*PC;
    float4 df = {0,0,0,0}, db = {0,0,0,0}, qq = {0,0,0,0};
    #pragma unroll 8
    for (int c = 0; c < PC; c++) {
        float4 v = *(const float4*)(qb + (size_t)c*N);
        float f = fp[c], p = bp[c];
        df.x += v.x*f; df.y += v.y*f; df.z += v.z*f; df.w += v.w*f;
        db.x += v.x*p; db.y += v.y*p; db.z += v.z*p; db.w += v.w*p;
        qq.x += v.x*v.x; qq.y += v.y*v.y; qq.z += v.z*v.z; qq.w += v.w*v.w;
    }
    int g = b*N + n;
    *(float4*)&g_pdf[chunk][g] = df;
    *(float4*)&g_pdb[chunk][g] = db;
    *(float4*)&g_pqq[chunk][g] = qq;
}

// ---------------- K2b: inline norms + combine + softmax epilogue (+ zero denom) ----------------
__global__ void k_pred2() {
    __shared__ float sh[256];
    __shared__ float snF, snB;
    int t = threadIdx.x;
    int g = blockIdx.x * 256 + t;
    int b = g / N;
    // proto norms (per-block redundant reduce; FP/BP are L2/L1-hot)
    float a0 = g_FP[b*C + t], a1 = g_FP[b*C + 256 + t];
    sh[t] = a0*a0 + a1*a1; __syncthreads();
    for (int off = 128; off > 0; off >>= 1) { if (t < off) sh[t] += sh[t+off]; __syncthreads(); }
    if (t == 0) snF = sqrtf(sh[0]);
    __syncthreads();
    float p0 = g_BP[b*C + t], p1 = g_BP[b*C + 256 + t];
    sh[t] = p0*p0 + p1*p1; __syncthreads();
    for (int off = 128; off > 0; off >>= 1) { if (t < off) sh[t] += sh[t+off]; __syncthreads(); }
    if (t == 0) snB = sqrtf(sh[0]);
    __syncthreads();

    float df = 0.f, db = 0.f, qq = 0.f;
    #pragma unroll
    for (int k = 0; k < NCHP; k++) {
        df += g_pdf[k][g];
        db += g_pdb[k][g];
        qq += g_pqq[k][g];
    }
    float nq = sqrtf(qq);
    float sf = 10.f * df / fmaxf(nq * snF, 1e-8f);
    float sb = 10.f * db / fmaxf(nq * snB, 1e-8f);
    float mx = fmaxf(sf, sb);
    float ef = expf(sf - mx), eb = expf(sb - mx);
    float inv = 1.f / (ef + eb);
    g_predfg[g] = ef * inv;
    g_predbg[g] = eb * inv;
    g_qn[g] = nq;
    g_invn[g] = 1.f / fmaxf(nq, 1e-20f);
    g_denom[g] = 0.f;          // cleared for k5's atomic row sums
}

// ---------------- K3: threshold / top-12 selection (shfl argmax + ballot scan) ----------------
__global__ void k_weights() {
    int which = blockIdx.x;   // 0 = fg, 1 = bg
    int b = blockIdx.y;
    int tid = threadIdx.x;
    int lane = tid & 31, w = tid >> 5;
    const float* pred = which ? (g_predbg + b*N) : (g_predfg + b*N);
    float thres = which ? 0.6f : 0.7f;
    float p = pred[tid];
    int flag = (p > thres) ? 1 : 0;
    int cnt = __syncthreads_count(flag);

    __shared__ float shv[32];
    __shared__ int   shi[32];
    __shared__ int   swin;

    bool sel;
    if (cnt > 0) {
        sel = (flag != 0);
    } else {
        bool taken = false;
        for (int it = 0; it < TOPK; it++) {
            float v = taken ? -1e30f : p;
            int id = tid;
            #pragma unroll
            for (int off = 16; off > 0; off >>= 1) {
                float ov = __shfl_down_sync(0xffffffffu, v, off);
                int   oi = __shfl_down_sync(0xffffffffu, id, off);
                if (ov > v || (ov == v && oi < id)) { v = ov; id = oi; }
            }
            if (lane == 0) { shv[w] = v; shi[w] = id; }
            __syncthreads();
            if (w == 0) {
                float v2 = shv[lane]; int i2 = shi[lane];
                #pragma unroll
                for (int off = 16; off > 0; off >>= 1) {
                    float ov = __shfl_down_sync(0xffffffffu, v2, off);
                    int   oi = __shfl_down_sync(0xffffffffu, i2, off);
                    if (ov > v2 || (ov == v2 && oi < i2)) { v2 = ov; i2 = oi; }
                }
                if (lane == 0) swin = i2;
            }
            __syncthreads();
            if (tid == swin) taken = true;
        }
        sel = taken;
    }

    float wsum = (cnt > 0) ? (float)cnt : (float)TOPK;
    if (which == 0) {
        g_wf[b*N + tid] = sel ? 1.f : 0.f;
        if (tid == 0) g_wfsum[b] = wsum;
    } else {
        __shared__ int wtot[32];
        __shared__ int wbase[33];
        unsigned bal = __ballot_sync(0xffffffffu, sel);
        int wincl = __popc(bal & (0xffffffffu >> (31 - lane)));
        if (lane == 31) wtot[w] = wincl;
        __syncthreads();
        if (w == 0) {
            int tv = wtot[lane];
            int x = tv;
            #pragma unroll
            for (int off = 1; off < 32; off <<= 1) {
                int y = __shfl_up_sync(0xffffffffu, x, off);
                if (lane >= off) x += y;
            }
            wbase[lane] = x - tv;
            if (lane == 31) wbase[32] = x;
        }
        __syncthreads();
        if (sel) {
            int pos = wbase[w] + wincl - 1;
            g_idx[b*N + pos]  = tid;
            g_invg[b*N + pos] = g_invn[b*N + tid];
        }
        if (tid == 0) {
            int M = wbase[32];
            g_M[b] = M;
            g_Mpad[b] = (M + 63) & ~63;
        }
    }
}

// ---------------- K3b: fused fg-proto + tf32 q copy + gather(tf32) + bg-proto ----------------
__global__ void k_gfg(const float* __restrict__ q) {
    int bc = blockIdx.x;
    int b = bc / C;
    int t = threadIdx.x, lane = t & 31, w = t >> 5;
    __shared__ float sh[4];

    const float4* row4 = (const float4*)(q + (size_t)bc*N);
    const float4* wf4  = (const float4*)(g_wf + b*N);
    uint4* qt4 = (uint4*)(g_qt + (size_t)bc*N);
    float s = 0.f;
    #pragma unroll
    for (int i = 0; i < 2; i++) {
        int p = t + i*128;
        float4 v = row4[p], wv = wf4[p];
        s += v.x*wv.x + v.y*wv.y + v.z*wv.z + v.w*wv.w;
        uint4 u;
        u.x = f2tf32(v.x); u.y = f2tf32(v.y); u.z = f2tf32(v.z); u.w = f2tf32(v.w);
        qt4[p] = u;
    }
    s = warp_sum(s);
    if (lane == 0) sh[w] = s;
    __syncthreads();
    if (t == 0) g_fgp[bc] = (sh[0]+sh[1]+sh[2]+sh[3]) / g_wfsum[b];

    int Mb = g_M[b], Mpad = g_Mpad[b];
    const int* idx = g_idx + b*N;
    const float* row = q + (size_t)bc*N;
    uint32_t* vrow = g_Vg + (size_t)bc*N;
    float sb = 0.f;
    for (int m = t; m < Mb; m += 128) {       // row is L1-hot from the pass above
        float v = row[idx[m]];
        vrow[m] = f2tf32(v);
        sb += v;
    }
    for (int m = Mb + t; m < Mpad; m += 128) vrow[m] = 0u;
    sb = warp_sum(sb);
    __syncthreads();
    if (lane == 0) sh[w] = sb;
    __syncthreads();
    if (t == 0) g_bgp[bc] = (sh[0]+sh[1]+sh[2]+sh[3]) / (float)Mb;
}

// ---------------- K5: S = exp(2 cn^T cn) via tf32 mma (pure copies) + fused denom ----------------
__global__ __launch_bounds__(256) void k5_mma() {
    int b  = blockIdx.z;
    int i0 = blockIdx.y * 64;
    int m0 = blockIdx.x * 64;
    int Mb = g_M[b];
    int Mpad = g_Mpad[b];
    if (m0 >= Mpad) return;

    __shared__ uint32_t As[32][72];
    __shared__ uint32_t Bs[32][72];

    int t = threadIdx.x;
    int lane = t & 31, w = t >> 5;
    int gid = lane >> 2, tig = lane & 3;
    int iw = (w >> 1) * 16;
    int mw = (w & 1) * 32;

    float acc[4][4] = {};

    const uint32_t* qb = g_qt + (size_t)b*C*N;
    const uint32_t* vg = g_Vg + (size_t)b*C*N;

    int lr = t >> 4;
    int lc = (t & 15) * 4;

    for (int k0 = 0; k0 < C; k0 += 32) {
        #pragma unroll
        for (int rr = 0; rr < 2; rr++) {
            int k = lr + rr * 16;
            *(uint4*)&As[k][lc] = *(const uint4*)(qb + (size_t)(k0 + k)*N + i0 + lc);
            *(uint4*)&Bs[k][lc] = *(const uint4*)(vg + (size_t)(k0 + k)*N + m0 + lc);
        }
        __syncthreads();
        #pragma unroll
        for (int kk = 0; kk < 32; kk += 8) {
            uint32_t a0 = As[kk + tig    ][iw + gid];
            uint32_t a1 = As[kk + tig    ][iw + gid + 8];
            uint32_t a2 = As[kk + 4 + tig][iw + gid];
            uint32_t a3 = As[kk + 4 + tig][iw + gid + 8];
            #pragma unroll
            for (int j = 0; j < 4; j++) {
                uint32_t b0 = Bs[kk + tig    ][mw + 8*j + gid];
                uint32_t b1 = Bs[kk + 4 + tig][mw + 8*j + gid];
                mma_tf32(acc[j], a0, a1, a2, a3, b0, b1);
            }
        }
        __syncthreads();
    }

    int ilo = i0 + iw + gid;
    int ihi = ilo + 8;
    float invlo = g_invn[b*N + ilo];
    float invhi = g_invn[b*N + ihi];
    float slo = 0.f, shi2 = 0.f;
    #pragma unroll
    for (int j = 0; j < 4; j++) {
        int m = m0 + mw + 8*j + 2*tig;
        bool in0 = m < Mb, in1 = (m + 1) < Mb;
        float ig0 = in0 ? g_invg[b*N + m]     : 0.f;
        float ig1 = in1 ? g_invg[b*N + m + 1] : 0.f;
        float e00 = in0 ? __expf(2.f * acc[j][0] * invlo * ig0) : 0.f;
        float e01 = in1 ? __expf(2.f * acc[j][1] * invlo * ig1) : 0.f;
        float e10 = in0 ? __expf(2.f * acc[j][2] * invhi * ig0) : 0.f;
        float e11 = in1 ? __expf(2.f * acc[j][3] * invhi * ig1) : 0.f;
        uint32_t* r0 = g_S + ((size_t)b*N + ilo)*N + m;
        uint32_t* r1 = g_S + ((size_t)b*N + ihi)*N + m;
        r0[0] = in0 ? f2tf32(e00) : 0u; r0[1] = in1 ? f2tf32(e01) : 0u;
        r1[0] = in0 ? f2tf32(e10) : 0u; r1[1] = in1 ? f2tf32(e11) : 0u;
        slo  += e00 + e01;
        shi2 += e10 + e11;
    }
    slo  += __shfl_xor_sync(0xffffffffu, slo, 1);
    slo  += __shfl_xor_sync(0xffffffffu, slo, 2);
    shi2 += __shfl_xor_sync(0xffffffffu, shi2, 1);
    shi2 += __shfl_xor_sync(0xffffffffu, shi2, 2);
    if (tig == 0) {
        atomicAdd(&g_denom[b*N + ilo], slo);
        atomicAdd(&g_denom[b*N + ihi], shi2);
    }
}

// ---------------- K7: bg_local GEMM (pure copies) + fused FP1 + final-similarity partials ----------------
__global__ __launch_bounds__(256) void k7_mma(const float* __restrict__ q) {
    int b  = blockIdx.z;
    int c0 = blockIdx.y * 64;
    int i0 = blockIdx.x * 64;
    int Mpad = g_Mpad[b];

    __shared__ float sraw[4608];   // aliased: As/Bs (2*64*36 u32) then bp tile (64*65 f32)
    #define K7_AS(r,c) (((uint32_t*)sraw)[(r)*36+(c)])
    #define K7_BS(r,c) (((uint32_t*)sraw)[2304+(r)*36+(c)])
    #define K7_BP(r,c) (sraw[(r)*65+(c)])

    int t = threadIdx.x;
    int lane = t & 31, w = t >> 5;
    int gid = lane >> 2, tig = lane & 3;
    int cw = (w >> 1) * 16;
    int iw = (w & 1) * 32;

    float acc[4][4] = {};

    int lr = t >> 3;
    int lc = (t & 7) * 4;

    for (int m0 = 0; m0 < Mpad; m0 += 32) {
        #pragma unroll
        for (int rr = 0; rr < 2; rr++) {
            int r = lr + rr * 32;
            *(uint4*)&K7_AS(r,lc) = *(const uint4*)(g_Vg + ((size_t)b*C + c0 + r)*N + m0 + lc);
            *(uint4*)&K7_BS(r,lc) = *(const uint4*)(g_S  + ((size_t)b*N + i0 + r)*N + m0 + lc);
        }
        __syncthreads();
        #pragma unroll
        for (int kk = 0; kk < 32; kk += 8) {
            uint32_t a0 = K7_AS(cw + gid    , kk + tig);
            uint32_t a1 = K7_AS(cw + gid + 8, kk + tig);
            uint32_t a2 = K7_AS(cw + gid    , kk + 4 + tig);
            uint32_t a3 = K7_AS(cw + gid + 8, kk + 4 + tig);
            #pragma unroll
            for (int j = 0; j < 4; j++) {
                uint32_t b0 = K7_BS(iw + 8*j + gid, kk + tig);
                uint32_t b1 = K7_BS(iw + 8*j + gid, kk + 4 + tig);
                mma_tf32(acc[j], a0, a1, a2, a3, b0, b1);
            }
        }
        __syncthreads();
    }

    // epilogue: bp tile into smem
    int clo = c0 + cw + gid;
    float bglo = 0.3f * g_bgp[b*C + clo];
    float bghi = 0.3f * g_bgp[b*C + clo + 8];
    #pragma unroll
    for (int j = 0; j < 4; j++) {
        int i = iw + 8*j + 2*tig;
        float d0 = 0.7f / g_denom[b*N + i0 + i];
        float d1 = 0.7f / g_denom[b*N + i0 + i + 1];
        K7_BP(cw + gid    , i  ) = bglo + acc[j][0] * d0;
        K7_BP(cw + gid    , i+1) = bglo + acc[j][1] * d1;
        K7_BP(cw + gid + 8, i  ) = bghi + acc[j][2] * d0;
        K7_BP(cw + gid + 8, i+1) = bghi + acc[j][3] * d1;
    }
    __syncthreads();

    // reduction: 4 threads per pixel, 16 channels each; FP1 computed on the fly
    int px = t >> 2;
    int cs = (t & 3) * 16;
    int i = i0 + px;
    const float* qcol = q + ((size_t)b*C + c0 + cs)*N + i;
    const float* fpv  = g_FP  + b*C + c0 + cs;
    const float* fgv  = g_fgp + b*C + c0 + cs;
    float sdf = 0.f, sdb = 0.f, sbb = 0.f;
    #pragma unroll
    for (int k = 0; k < 16; k++) {
        float qv = qcol[(size_t)k*N];
        float bp = K7_BP(cs + k, px);
        sdf += qv * (0.5f * (fpv[k] + fgv[k]));
        sdb += qv * bp;
        sbb += bp * bp;
    }
    sdf += __shfl_xor_sync(0xffffffffu, sdf, 1);
    sdf += __shfl_xor_sync(0xffffffffu, sdf, 2);
    sdb += __shfl_xor_sync(0xffffffffu, sdb, 1);
    sdb += __shfl_xor_sync(0xffffffffu, sdb, 2);
    sbb += __shfl_xor_sync(0xffffffffu, sbb, 1);
    sbb += __shfl_xor_sync(0xffffffffu, sbb, 2);
    if ((t & 3) == 0) {
        int cb = blockIdx.y;
        g_odf[cb][b*N + i] = sdf;
        g_odb[cb][b*N + i] = sdb;
        g_obb[cb][b*N + i] = sbb;
    }
    #undef K7_AS
    #undef K7_BS
    #undef K7_BP
}

// ---------------- K8: inline nFP1 + combine partials + write output ----------------
__global__ void k_out2(float* __restrict__ out) {
    __shared__ float sh[256];
    __shared__ float snF1;
    int t = threadIdx.x;
    int g = blockIdx.x * 256 + t;
    int b = g / N, n = g % N;
    float v0 = 0.5f * (g_FP[b*C + t]       + g_fgp[b*C + t]);
    float v1 = 0.5f * (g_FP[b*C + 256 + t] + g_fgp[b*C + 256 + t]);
    sh[t] = v0*v0 + v1*v1; __syncthreads();
    for (int off = 128; off > 0; off >>= 1) { if (t < off) sh[t] += sh[t+off]; __syncthreads(); }
    if (t == 0) snF1 = sqrtf(sh[0]);
    __syncthreads();

    float df = 0.f, db = 0.f, bb = 0.f;
    #pragma unroll
    for (int k = 0; k < OC; k++) {
        df += g_odf[k][g];
        db += g_odb[k][g];
        bb += g_obb[k][g];
    }
    float nq = g_qn[g];
    float nb = sqrtf(bb);
    out[(b*2 + 0)*N + n] = 10.f * db / fmaxf(nq * nb, 1e-8f);
    out[(b*2 + 1)*N + n] = 10.f * df / fmaxf(nq * snF1, 1e-8f);
}

// ---------------- launch ----------------
extern "C" void kernel_launch(void* const* d_in, const int* in_sizes, int n_in,
                              void* d_out, int out_size) {
    const float* q    = (const float*)d_in[0];
    const float* sf   = (const float*)d_in[1];
    const int*   mask = (const int*)d_in[2];
    float* out = (float*)d_out;

    k_pool   <<<B*C/8, 256>>>(sf, mask);
    k_pred1  <<<dim3(B*N/1024, NCHP), 256>>>(q);
    k_pred2  <<<B*N/256, 256>>>();
    k_weights<<<dim3(2, B), 1024>>>();
    k_gfg    <<<B*C, 128>>>(q);
    k5_mma   <<<dim3(N/64, N/64, B), 256>>>();
    k7_mma   <<<dim3(N/64, C/64, B), 256>>>(q);
    k_out2   <<<B*N/256, 256>>>(out);
}

// round 11
// speedup vs baseline: 1.1273x; 1.1273x over previous
#include <cuda_runtime.h>
#include <math.h>
#include <stdint.h>

#define B 8
#define C 512
#define N 1024
#define TOPK 12
#define NCHP 16
#define PC (C/NCHP)     // 32 channels per pred chunk
#define OC 8            // output c-blocks (C/64)

// ---------------- device scratch (no allocations allowed) ----------------
__device__ float g_FP[B*C], g_BP[B*C];
__device__ float g_predfg[B*N], g_predbg[B*N];
__device__ float g_invn[B*N], g_qn[B*N];
__device__ float g_wf[B*N];
__device__ float g_wfsum[B];
__device__ int   g_idx[B*N];
__device__ int   g_M[B];
__device__ int   g_Mpad[B];
__device__ float g_invg[B*N];
__device__ float g_Vg[(size_t)B*C*N];        // gathered active columns (zero-padded to Mpad)
__device__ float g_S[(size_t)B*N*N];         // exp scores (N x Mpad per batch, zero beyond Mb)
__device__ float g_denom[B*N];
__device__ float g_fgp[B*C], g_bgp[B*C];

// split partials
__device__ float g_pdf[NCHP][B*N], g_pdb[NCHP][B*N], g_pqq[NCHP][B*N];
__device__ float g_odf[OC][B*N], g_odb[OC][B*N], g_obb[OC][B*N];

// ---------------- helpers ----------------
__device__ __forceinline__ float warp_sum(float v) {
    #pragma unroll
    for (int off = 16; off > 0; off >>= 1) v += __shfl_down_sync(0xffffffffu, v, off);
    return v;
}

__device__ __forceinline__ uint32_t f2tf32(float f) {
    uint32_t u;
    asm("cvt.rna.tf32.f32 %0, %1;" : "=r"(u) : "f"(f));
    return u;
}

__device__ __forceinline__ void mma_tf32(float c[4],
                                         uint32_t a0, uint32_t a1, uint32_t a2, uint32_t a3,
                                         uint32_t b0, uint32_t b1) {
    asm volatile("mma.sync.aligned.m16n8k8.row.col.f32.tf32.tf32.f32 "
                 "{%0,%1,%2,%3}, {%4,%5,%6,%7}, {%8,%9}, {%0,%1,%2,%3};"
                 : "+f"(c[0]), "+f"(c[1]), "+f"(c[2]), "+f"(c[3])
                 : "r"(a0), "r"(a1), "r"(a2), "r"(a3), "r"(b0), "r"(b1));
}

// ---------------- K1: masked avg pool (FP/BP) + inline counts, one warp per (b,c) ----------------
__global__ void k_pool(const float* __restrict__ sf, const int* __restrict__ mask) {
    int w = blockIdx.x * 8 + (threadIdx.x >> 5);
    int lane = threadIdx.x & 31;
    int b = w / C, c = w % C;
    const float4* row4 = (const float4*)(sf + (size_t)w*N);
    const int4*   m4   = (const int4*)(mask + b*N);
    float s1 = 0.f, s0 = 0.f, c1 = 0.f;
    #pragma unroll
    for (int i = 0; i < 8; i++) {
        int p = lane + i*32;
        float4 v = row4[p];
        int4 mk = m4[p];
        float fx = (float)mk.x, fy = (float)mk.y, fz = (float)mk.z, fw = (float)mk.w;
        s1 += fx*v.x + fy*v.y + fz*v.z + fw*v.w;
        s0 += (1.f-fx)*v.x + (1.f-fy)*v.y + (1.f-fz)*v.z + (1.f-fw)*v.w;
        c1 += fx + fy + fz + fw;
    }
    s1 = warp_sum(s1); s0 = warp_sum(s0); c1 = warp_sum(c1);
    if (lane == 0) {
        g_FP[b*C + c] = s1 / (c1 + 1e-5f);
        g_BP[b*C + c] = s0 / ((float)N - c1 + 1e-5f);
    }
}

// ---------------- K2a: split-C partial dot products for pred (R9 form) ----------------
__global__ __launch_bounds__(256) void k_pred1(const float* __restrict__ q) {
    int g = blockIdx.x * blockDim.x + threadIdx.x;   // pixel id (b*N+n)
    int chunk = blockIdx.y;
    int b = g / N, n = g % N;
    const float* qb = q + (size_t)b*C*N + (size_t)chunk*PC*N + n;
    const float* fp = g_FP + b*C + chunk*PC;
    const float* bp = g_BP + b*C + chunk*PC;
    float df = 0.f, db = 0.f, qq = 0.f;
    #pragma unroll 16
    for (int c = 0; c < PC; c++) {
        float v = qb[(size_t)c*N];
        df += v * fp[c];
        db += v * bp[c];
        qq += v * v;
    }
    g_pdf[chunk][g] = df;
    g_pdb[chunk][g] = db;
    g_pqq[chunk][g] = qq;
}

// ---------------- K2b: inline norms + combine + softmax epilogue (+ zero denom) ----------------
__global__ void k_pred2() {
    __shared__ float sh[256];
    __shared__ float snF, snB;
    int t = threadIdx.x;
    int g = blockIdx.x * 256 + t;
    int b = g / N;
    float a0 = g_FP[b*C + t], a1 = g_FP[b*C + 256 + t];
    sh[t] = a0*a0 + a1*a1; __syncthreads();
    for (int off = 128; off > 0; off >>= 1) { if (t < off) sh[t] += sh[t+off]; __syncthreads(); }
    if (t == 0) snF = sqrtf(sh[0]);
    __syncthreads();
    float p0 = g_BP[b*C + t], p1 = g_BP[b*C + 256 + t];
    sh[t] = p0*p0 + p1*p1; __syncthreads();
    for (int off = 128; off > 0; off >>= 1) { if (t < off) sh[t] += sh[t+off]; __syncthreads(); }
    if (t == 0) snB = sqrtf(sh[0]);
    __syncthreads();

    float df = 0.f, db = 0.f, qq = 0.f;
    #pragma unroll
    for (int k = 0; k < NCHP; k++) {
        df += g_pdf[k][g];
        db += g_pdb[k][g];
        qq += g_pqq[k][g];
    }
    float nq = sqrtf(qq);
    float sf = 10.f * df / fmaxf(nq * snF, 1e-8f);
    float sb = 10.f * db / fmaxf(nq * snB, 1e-8f);
    float mx = fmaxf(sf, sb);
    float ef = expf(sf - mx), eb = expf(sb - mx);
    float inv = 1.f / (ef + eb);
    g_predfg[g] = ef * inv;
    g_predbg[g] = eb * inv;
    g_qn[g] = nq;
    g_invn[g] = 1.f / fmaxf(nq, 1e-20f);
    g_denom[g] = 0.f;
}

// ---------------- K3: threshold / top-12 selection (shfl argmax + ballot scan) ----------------
__global__ void k_weights() {
    int which = blockIdx.x;   // 0 = fg, 1 = bg
    int b = blockIdx.y;
    int tid = threadIdx.x;
    int lane = tid & 31, w = tid >> 5;
    const float* pred = which ? (g_predbg + b*N) : (g_predfg + b*N);
    float thres = which ? 0.6f : 0.7f;
    float p = pred[tid];
    int flag = (p > thres) ? 1 : 0;
    int cnt = __syncthreads_count(flag);

    __shared__ float shv[32];
    __shared__ int   shi[32];
    __shared__ int   swin;

    bool sel;
    if (cnt > 0) {
        sel = (flag != 0);
    } else {
        bool taken = false;
        for (int it = 0; it < TOPK; it++) {
            float v = taken ? -1e30f : p;
            int id = tid;
            #pragma unroll
            for (int off = 16; off > 0; off >>= 1) {
                float ov = __shfl_down_sync(0xffffffffu, v, off);
                int   oi = __shfl_down_sync(0xffffffffu, id, off);
                if (ov > v || (ov == v && oi < id)) { v = ov; id = oi; }
            }
            if (lane == 0) { shv[w] = v; shi[w] = id; }
            __syncthreads();
            if (w == 0) {
                float v2 = shv[lane]; int i2 = shi[lane];
                #pragma unroll
                for (int off = 16; off > 0; off >>= 1) {
                    float ov = __shfl_down_sync(0xffffffffu, v2, off);
                    int   oi = __shfl_down_sync(0xffffffffu, i2, off);
                    if (ov > v2 || (ov == v2 && oi < i2)) { v2 = ov; i2 = oi; }
                }
                if (lane == 0) swin = i2;
            }
            __syncthreads();
            if (tid == swin) taken = true;
        }
        sel = taken;
    }

    float wsum = (cnt > 0) ? (float)cnt : (float)TOPK;
    if (which == 0) {
        g_wf[b*N + tid] = sel ? 1.f : 0.f;
        if (tid == 0) g_wfsum[b] = wsum;
    } else {
        __shared__ int wtot[32];
        __shared__ int wbase[33];
        unsigned bal = __ballot_sync(0xffffffffu, sel);
        int wincl = __popc(bal & (0xffffffffu >> (31 - lane)));
        if (lane == 31) wtot[w] = wincl;
        __syncthreads();
        if (w == 0) {
            int tv = wtot[lane];
            int x = tv;
            #pragma unroll
            for (int off = 1; off < 32; off <<= 1) {
                int y = __shfl_up_sync(0xffffffffu, x, off);
                if (lane >= off) x += y;
            }
            wbase[lane] = x - tv;
            if (lane == 31) wbase[32] = x;
        }
        __syncthreads();
        if (sel) {
            int pos = wbase[w] + wincl - 1;
            g_idx[b*N + pos]  = tid;
            g_invg[b*N + pos] = g_invn[b*N + tid];
        }
        if (tid == 0) {
            int M = wbase[32];
            g_M[b] = M;
            g_Mpad[b] = (M + 63) & ~63;
        }
    }
}

// ---------------- K3b: fused fg-proto + gather + bg-proto (R9 form) ----------------
__global__ void k_gfg(const float* __restrict__ q) {
    int bc = blockIdx.x;
    int b = bc / C;
    int t = threadIdx.x, lane = t & 31, w = t >> 5;
    __shared__ float sh[4];

    const float4* row4 = (const float4*)(q + (size_t)bc*N);
    const float4* wf4  = (const float4*)(g_wf + b*N);
    float s = 0.f;
    #pragma unroll
    for (int i = 0; i < 2; i++) {
        int p = t + i*128;
        float4 v = row4[p], wv = wf4[p];
        s += v.x*wv.x + v.y*wv.y + v.z*wv.z + v.w*wv.w;
    }
    s = warp_sum(s);
    if (lane == 0) sh[w] = s;
    __syncthreads();
    if (t == 0) g_fgp[bc] = (sh[0]+sh[1]+sh[2]+sh[3]) / g_wfsum[b];

    int Mb = g_M[b], Mpad = g_Mpad[b];
    const int* idx = g_idx + b*N;
    const float* row = q + (size_t)bc*N;
    float* vrow = g_Vg + (size_t)bc*N;
    float sb = 0.f;
    for (int m = t; m < Mb; m += 128) {       // row is L1-hot from the pass above
        float v = row[idx[m]];
        vrow[m] = v;
        sb += v;
    }
    for (int m = Mb + t; m < Mpad; m += 128) vrow[m] = 0.f;
    sb = warp_sum(sb);
    __syncthreads();
    if (lane == 0) sh[w] = sb;
    __syncthreads();
    if (t == 0) g_bgp[bc] = (sh[0]+sh[1]+sh[2]+sh[3]) / (float)Mb;
}

// ---------------- K5: S = exp(2 cn^T cn), 4 warps of 32x32 tiles + fused denom ----------------
__global__ __launch_bounds__(128) void k5_mma(const float* __restrict__ q) {
    int b  = blockIdx.z;
    int i0 = blockIdx.y * 64;
    int m0 = blockIdx.x * 64;
    int Mb = g_M[b];
    int Mpad = g_Mpad[b];
    if (m0 >= Mpad) return;

    __shared__ uint32_t As[32][72];
    __shared__ uint32_t Bs[32][72];

    int t = threadIdx.x;
    int lane = t & 31, w = t >> 5;
    int gid = lane >> 2, tig = lane & 3;
    int iw = (w >> 1) * 32;
    int mw = (w & 1) * 32;

    float acc[2][4][4] = {};

    const float* qb = q + (size_t)b*C*N;
    const float* vg = g_Vg + (size_t)b*C*N;

    int lr = t >> 4;              // 0..7
    int lc = (t & 15) * 4;        // 0..60

    for (int k0 = 0; k0 < C; k0 += 32) {
        #pragma unroll
        for (int rr = 0; rr < 4; rr++) {
            int k = lr + rr * 8;
            float4 va = *(const float4*)(qb + (size_t)(k0 + k)*N + i0 + lc);
            As[k][lc+0] = f2tf32(va.x); As[k][lc+1] = f2tf32(va.y);
            As[k][lc+2] = f2tf32(va.z); As[k][lc+3] = f2tf32(va.w);
            float4 vb = *(const float4*)(vg + (size_t)(k0 + k)*N + m0 + lc);
            Bs[k][lc+0] = f2tf32(vb.x); Bs[k][lc+1] = f2tf32(vb.y);
            Bs[k][lc+2] = f2tf32(vb.z); Bs[k][lc+3] = f2tf32(vb.w);
        }
        __syncthreads();
        #pragma unroll
        for (int kk = 0; kk < 32; kk += 8) {
            uint32_t a[2][4];
            #pragma unroll
            for (int ti = 0; ti < 2; ti++) {
                a[ti][0] = As[kk + tig    ][iw + ti*16 + gid];
                a[ti][1] = As[kk + tig    ][iw + ti*16 + gid + 8];
                a[ti][2] = As[kk + 4 + tig][iw + ti*16 + gid];
                a[ti][3] = As[kk + 4 + tig][iw + ti*16 + gid + 8];
            }
            #pragma unroll
            for (int j = 0; j < 4; j++) {
                uint32_t b0 = Bs[kk + tig    ][mw + 8*j + gid];
                uint32_t b1 = Bs[kk + 4 + tig][mw + 8*j + gid];
                mma_tf32(acc[0][j], a[0][0], a[0][1], a[0][2], a[0][3], b0, b1);
                mma_tf32(acc[1][j], a[1][0], a[1][1], a[1][2], a[1][3], b0, b1);
            }
        }
        __syncthreads();
    }

    #pragma unroll
    for (int ti = 0; ti < 2; ti++) {
        int ilo = i0 + iw + ti*16 + gid;
        int ihi = ilo + 8;
        float invlo = g_invn[b*N + ilo];
        float invhi = g_invn[b*N + ihi];
        float slo = 0.f, shi2 = 0.f;
        #pragma unroll
        for (int j = 0; j < 4; j++) {
            int m = m0 + mw + 8*j + 2*tig;
            bool in0 = m < Mb, in1 = (m + 1) < Mb;
            float ig0 = in0 ? g_invg[b*N + m]     : 0.f;
            float ig1 = in1 ? g_invg[b*N + m + 1] : 0.f;
            float e00 = in0 ? __expf(2.f * acc[ti][j][0] * invlo * ig0) : 0.f;
            float e01 = in1 ? __expf(2.f * acc[ti][j][1] * invlo * ig1) : 0.f;
            float e10 = in0 ? __expf(2.f * acc[ti][j][2] * invhi * ig0) : 0.f;
            float e11 = in1 ? __expf(2.f * acc[ti][j][3] * invhi * ig1) : 0.f;
            float* r0 = g_S + ((size_t)b*N + ilo)*N + m;
            float* r1 = g_S + ((size_t)b*N + ihi)*N + m;
            r0[0] = e00; r0[1] = e01;
            r1[0] = e10; r1[1] = e11;
            slo  += e00 + e01;
            shi2 += e10 + e11;
        }
        slo  += __shfl_xor_sync(0xffffffffu, slo, 1);
        slo  += __shfl_xor_sync(0xffffffffu, slo, 2);
        shi2 += __shfl_xor_sync(0xffffffffu, shi2, 1);
        shi2 += __shfl_xor_sync(0xffffffffu, shi2, 2);
        if (tig == 0) {
            atomicAdd(&g_denom[b*N + ilo], slo);
            atomicAdd(&g_denom[b*N + ihi], shi2);
        }
    }
}

// ---------------- K7: bg_local GEMM (4 warps of 32x32) + fused FP1 + final partials ----------------
__global__ __launch_bounds__(128) void k7_mma(const float* __restrict__ q) {
    int b  = blockIdx.z;
    int c0 = blockIdx.y * 64;
    int i0 = blockIdx.x * 64;
    int Mpad = g_Mpad[b];

    __shared__ float sraw[4608];   // aliased: As/Bs (2*64*36 u32) then bp tile (64*65 f32)
    #define K7_AS(r,c) (((uint32_t*)sraw)[(r)*36+(c)])
    #define K7_BS(r,c) (((uint32_t*)sraw)[2304+(r)*36+(c)])
    #define K7_BP(r,c) (sraw[(r)*65+(c)])

    int t = threadIdx.x;
    int lane = t & 31, w = t >> 5;
    int gid = lane >> 2, tig = lane & 3;
    int cw = (w >> 1) * 32;
    int iw = (w & 1) * 32;

    float acc[2][4][4] = {};

    int lr = t >> 3;              // 0..15
    int lc = (t & 7) * 4;         // 0..28

    for (int m0 = 0; m0 < Mpad; m0 += 32) {
        #pragma unroll
        for (int rr = 0; rr < 4; rr++) {
            int r = lr + rr * 16;
            float4 va = *(const float4*)(g_Vg + ((size_t)b*C + c0 + r)*N + m0 + lc);
            K7_AS(r,lc+0) = f2tf32(va.x); K7_AS(r,lc+1) = f2tf32(va.y);
            K7_AS(r,lc+2) = f2tf32(va.z); K7_AS(r,lc+3) = f2tf32(va.w);
            float4 vb = *(const float4*)(g_S + ((size_t)b*N + i0 + r)*N + m0 + lc);
            K7_BS(r,lc+0) = f2tf32(vb.x); K7_BS(r,lc+1) = f2tf32(vb.y);
            K7_BS(r,lc+2) = f2tf32(vb.z); K7_BS(r,lc+3) = f2tf32(vb.w);
        }
        __syncthreads();
        #pragma unroll
        for (int kk = 0; kk < 32; kk += 8) {
            uint32_t a[2][4];
            #pragma unroll
            for (int tc = 0; tc < 2; tc++) {
                a[tc][0] = K7_AS(cw + tc*16 + gid    , kk + tig);
                a[tc][1] = K7_AS(cw + tc*16 + gid + 8, kk + tig);
                a[tc][2] = K7_AS(cw + tc*16 + gid    , kk + 4 + tig);
                a[tc][3] = K7_AS(cw + tc*16 + gid + 8, kk + 4 + tig);
            }
            #pragma unroll
            for (int j = 0; j < 4; j++) {
                uint32_t b0 = K7_BS(iw + 8*j + gid, kk + tig);
                uint32_t b1 = K7_BS(iw + 8*j + gid, kk + 4 + tig);
                mma_tf32(acc[0][j], a[0][0], a[0][1], a[0][2], a[0][3], b0, b1);
                mma_tf32(acc[1][j], a[1][0], a[1][1], a[1][2], a[1][3], b0, b1);
            }
        }
        __syncthreads();
    }

    // epilogue: bp tile into smem (FP1 applied later; bp = 0.3 bgp + 0.7 acc/denom)
    #pragma unroll
    for (int tc = 0; tc < 2; tc++) {
        int clo = c0 + cw + tc*16 + gid;
        float bglo = 0.3f * g_bgp[b*C + clo];
        float bghi = 0.3f * g_bgp[b*C + clo + 8];
        #pragma unroll
        for (int j = 0; j < 4; j++) {
            int i = iw + 8*j + 2*tig;
            float d0 = 0.7f / g_denom[b*N + i0 + i];
            float d1 = 0.7f / g_denom[b*N + i0 + i + 1];
            K7_BP(cw + tc*16 + gid    , i  ) = bglo + acc[tc][j][0] * d0;
            K7_BP(cw + tc*16 + gid    , i+1) = bglo + acc[tc][j][1] * d1;
            K7_BP(cw + tc*16 + gid + 8, i  ) = bghi + acc[tc][j][2] * d0;
            K7_BP(cw + tc*16 + gid + 8, i+1) = bghi + acc[tc][j][3] * d1;
        }
    }
    __syncthreads();

    // reduction: 2 threads per pixel, 32 channels each; FP1 computed on the fly
    int px = t >> 1;
    int cs = (t & 1) * 32;
    int i = i0 + px;
    const float* qcol = q + ((size_t)b*C + c0 + cs)*N + i;
    const float* fpv  = g_FP  + b*C + c0 + cs;
    const float* fgv  = g_fgp + b*C + c0 + cs;
    float sdf = 0.f, sdb = 0.f, sbb = 0.f;
    #pragma unroll
    for (int k = 0; k < 32; k++) {
        float qv = qcol[(size_t)k*N];
        float bp = K7_BP(cs + k, px);
        sdf += qv * (0.5f * (fpv[k] + fgv[k]));
        sdb += qv * bp;
        sbb += bp * bp;
    }
    sdf += __shfl_xor_sync(0xffffffffu, sdf, 1);
    sdb += __shfl_xor_sync(0xffffffffu, sdb, 1);
    sbb += __shfl_xor_sync(0xffffffffu, sbb, 1);
    if ((t & 1) == 0) {
        int cb = blockIdx.y;
        g_odf[cb][b*N + i] = sdf;
        g_odb[cb][b*N + i] = sdb;
        g_obb[cb][b*N + i] = sbb;
    }
    #undef K7_AS
    #undef K7_BS
    #undef K7_BP
}

// ---------------- K8: inline nFP1 + combine partials + write output ----------------
__global__ void k_out2(float* __restrict__ out) {
    __shared__ float sh[256];
    __shared__ float snF1;
    int t = threadIdx.x;
    int g = blockIdx.x * 256 + t;
    int b = g / N, n = g % N;
    float v0 = 0.5f * (g_FP[b*C + t]       + g_fgp[b*C + t]);
    float v1 = 0.5f * (g_FP[b*C + 256 + t] + g_fgp[b*C + 256 + t]);
    sh[t] = v0*v0 + v1*v1; __syncthreads();
    for (int off = 128; off > 0; off >>= 1) { if (t < off) sh[t] += sh[t+off]; __syncthreads(); }
    if (t == 0) snF1 = sqrtf(sh[0]);
    __syncthreads();

    float df = 0.f, db = 0.f, bb = 0.f;
    #pragma unroll
    for (int k = 0; k < OC; k++) {
        df += g_odf[k][g];
        db += g_odb[k][g];
        bb += g_obb[k][g];
    }
    float nq = g_qn[g];
    float nb = sqrtf(bb);
    out[(b*2 + 0)*N + n] = 10.f * db / fmaxf(nq * nb, 1e-8f);
    out[(b*2 + 1)*N + n] = 10.f * df / fmaxf(nq * snF1, 1e-8f);
}

// ---------------- launch ----------------
extern "C" void kernel_launch(void* const* d_in, const int* in_sizes, int n_in,
                              void* d_out, int out_size) {
    const float* q    = (const float*)d_in[0];
    const float* sf   = (const float*)d_in[1];
    const int*   mask = (const int*)d_in[2];
    float* out = (float*)d_out;

    k_pool   <<<B*C/8, 256>>>(sf, mask);
    k_pred1  <<<dim3(B*N/256, NCHP), 256>>>(q);
    k_pred2  <<<B*N/256, 256>>>();
    k_weights<<<dim3(2, B), 1024>>>();
    k_gfg    <<<B*C, 128>>>(q);
    k5_mma   <<<dim3(N/64, N/64, B), 128>>>(q);
    k7_mma   <<<dim3(N/64, C/64, B), 128>>>(q);
    k_out2   <<<B*N/256, 256>>>(out);
}

// round 12
// speedup vs baseline: 1.2398x; 1.0998x over previous
#include <cuda_runtime.h>
#include <math.h>
#include <stdint.h>

#define B 8
#define C 512
#define N 1024
#define TOPK 12
#define NCHP 16
#define PC (C/NCHP)     // 32 channels per pred chunk
#define OC 8            // output c-blocks (C/64)

// ---------------- device scratch (no allocations allowed) ----------------
__device__ float g_FP[B*C], g_BP[B*C];
__device__ float g_predfg[B*N], g_predbg[B*N];
__device__ float g_invn[B*N], g_qn[B*N];
__device__ float g_wf[B*N];
__device__ float g_wfsum[B];
__device__ int   g_idx[B*N];
__device__ int   g_M[B];
__device__ int   g_Mpad[B];
__device__ float g_invg[B*N];
__device__ float g_Vg[(size_t)B*C*N];        // gathered active columns (zero-padded to Mpad)
__device__ float g_S[(size_t)B*N*N];         // exp scores (N x Mpad per batch, zero beyond Mb)
__device__ float g_denom[B*N];
__device__ float g_fgp[B*C], g_bgp[B*C];

// split partials
__device__ float g_pdf[NCHP][B*N], g_pdb[NCHP][B*N], g_pqq[NCHP][B*N];
__device__ float g_odf[OC][B*N], g_odb[OC][B*N], g_obb[OC][B*N];

// ---------------- helpers ----------------
__device__ __forceinline__ float warp_sum(float v) {
    #pragma unroll
    for (int off = 16; off > 0; off >>= 1) v += __shfl_down_sync(0xffffffffu, v, off);
    return v;
}

__device__ __forceinline__ uint32_t f2tf32(float f) {
    uint32_t u;
    asm("cvt.rna.tf32.f32 %0, %1;" : "=r"(u) : "f"(f));
    return u;
}

__device__ __forceinline__ void mma_tf32(float c[4],
                                         uint32_t a0, uint32_t a1, uint32_t a2, uint32_t a3,
                                         uint32_t b0, uint32_t b1) {
    asm volatile("mma.sync.aligned.m16n8k8.row.col.f32.tf32.tf32.f32 "
                 "{%0,%1,%2,%3}, {%4,%5,%6,%7}, {%8,%9}, {%0,%1,%2,%3};"
                 : "+f"(c[0]), "+f"(c[1]), "+f"(c[2]), "+f"(c[3])
                 : "r"(a0), "r"(a1), "r"(a2), "r"(a3), "r"(b0), "r"(b1));
}

// ---------------- K1: masked avg pool (FP/BP) + inline counts, one warp per (b,c) ----------------
__global__ void k_pool(const float* __restrict__ sf, const int* __restrict__ mask) {
    int w = blockIdx.x * 8 + (threadIdx.x >> 5);
    int lane = threadIdx.x & 31;
    int b = w / C, c = w % C;
    const float4* row4 = (const float4*)(sf + (size_t)w*N);
    const int4*   m4   = (const int4*)(mask + b*N);
    float s1 = 0.f, s0 = 0.f, c1 = 0.f;
    #pragma unroll
    for (int i = 0; i < 8; i++) {
        int p = lane + i*32;
        float4 v = row4[p];
        int4 mk = m4[p];
        float fx = (float)mk.x, fy = (float)mk.y, fz = (float)mk.z, fw = (float)mk.w;
        s1 += fx*v.x + fy*v.y + fz*v.z + fw*v.w;
        s0 += (1.f-fx)*v.x + (1.f-fy)*v.y + (1.f-fz)*v.z + (1.f-fw)*v.w;
        c1 += fx + fy + fz + fw;
    }
    s1 = warp_sum(s1); s0 = warp_sum(s0); c1 = warp_sum(c1);
    if (lane == 0) {
        g_FP[b*C + c] = s1 / (c1 + 1e-5f);
        g_BP[b*C + c] = s0 / ((float)N - c1 + 1e-5f);
    }
}

// ---------------- K2a: split-C partial dot products for pred ----------------
__global__ __launch_bounds__(256) void k_pred1(const float* __restrict__ q) {
    int g = blockIdx.x * blockDim.x + threadIdx.x;   // pixel id (b*N+n)
    int chunk = blockIdx.y;
    int b = g / N, n = g % N;
    const float* qb = q + (size_t)b*C*N + (size_t)chunk*PC*N + n;
    const float* fp = g_FP + b*C + chunk*PC;
    const float* bp = g_BP + b*C + chunk*PC;
    float df = 0.f, db = 0.f, qq = 0.f;
    #pragma unroll 16
    for (int c = 0; c < PC; c++) {
        float v = qb[(size_t)c*N];
        df += v * fp[c];
        db += v * bp[c];
        qq += v * v;
    }
    g_pdf[chunk][g] = df;
    g_pdb[chunk][g] = db;
    g_pqq[chunk][g] = qq;
}

// ---------------- K2b: inline norms + combine + softmax epilogue (+ zero denom) ----------------
__global__ void k_pred2() {
    __shared__ float sh[256];
    __shared__ float snF, snB;
    int t = threadIdx.x;
    int g = blockIdx.x * 256 + t;
    int b = g / N;
    float a0 = g_FP[b*C + t], a1 = g_FP[b*C + 256 + t];
    sh[t] = a0*a0 + a1*a1; __syncthreads();
    for (int off = 128; off > 0; off >>= 1) { if (t < off) sh[t] += sh[t+off]; __syncthreads(); }
    if (t == 0) snF = sqrtf(sh[0]);
    __syncthreads();
    float p0 = g_BP[b*C + t], p1 = g_BP[b*C + 256 + t];
    sh[t] = p0*p0 + p1*p1; __syncthreads();
    for (int off = 128; off > 0; off >>= 1) { if (t < off) sh[t] += sh[t+off]; __syncthreads(); }
    if (t == 0) snB = sqrtf(sh[0]);
    __syncthreads();

    float df = 0.f, db = 0.f, qq = 0.f;
    #pragma unroll
    for (int k = 0; k < NCHP; k++) {
        df += g_pdf[k][g];
        db += g_pdb[k][g];
        qq += g_pqq[k][g];
    }
    float nq = sqrtf(qq);
    float sf = 10.f * df / fmaxf(nq * snF, 1e-8f);
    float sb = 10.f * db / fmaxf(nq * snB, 1e-8f);
    float mx = fmaxf(sf, sb);
    float ef = expf(sf - mx), eb = expf(sb - mx);
    float inv = 1.f / (ef + eb);
    g_predfg[g] = ef * inv;
    g_predbg[g] = eb * inv;
    g_qn[g] = nq;
    g_invn[g] = 1.f / fmaxf(nq, 1e-20f);
    g_denom[g] = 0.f;
}

// ---------------- K3: threshold / top-12 selection (shfl argmax + ballot scan) ----------------
__global__ void k_weights() {
    int which = blockIdx.x;   // 0 = fg, 1 = bg
    int b = blockIdx.y;
    int tid = threadIdx.x;
    int lane = tid & 31, w = tid >> 5;
    const float* pred = which ? (g_predbg + b*N) : (g_predfg + b*N);
    float thres = which ? 0.6f : 0.7f;
    float p = pred[tid];
    int flag = (p > thres) ? 1 : 0;
    int cnt = __syncthreads_count(flag);

    __shared__ float shv[32];
    __shared__ int   shi[32];
    __shared__ int   swin;

    bool sel;
    if (cnt > 0) {
        sel = (flag != 0);
    } else {
        bool taken = false;
        for (int it = 0; it < TOPK; it++) {
            float v = taken ? -1e30f : p;
            int id = tid;
            #pragma unroll
            for (int off = 16; off > 0; off >>= 1) {
                float ov = __shfl_down_sync(0xffffffffu, v, off);
                int   oi = __shfl_down_sync(0xffffffffu, id, off);
                if (ov > v || (ov == v && oi < id)) { v = ov; id = oi; }
            }
            if (lane == 0) { shv[w] = v; shi[w] = id; }
            __syncthreads();
            if (w == 0) {
                float v2 = shv[lane]; int i2 = shi[lane];
                #pragma unroll
                for (int off = 16; off > 0; off >>= 1) {
                    float ov = __shfl_down_sync(0xffffffffu, v2, off);
                    int   oi = __shfl_down_sync(0xffffffffu, i2, off);
                    if (ov > v2 || (ov == v2 && oi < i2)) { v2 = ov; i2 = oi; }
                }
                if (lane == 0) swin = i2;
            }
            __syncthreads();
            if (tid == swin) taken = true;
        }
        sel = taken;
    }

    float wsum = (cnt > 0) ? (float)cnt : (float)TOPK;
    if (which == 0) {
        g_wf[b*N + tid] = sel ? 1.f : 0.f;
        if (tid == 0) g_wfsum[b] = wsum;
    } else {
        __shared__ int wtot[32];
        __shared__ int wbase[33];
        unsigned bal = __ballot_sync(0xffffffffu, sel);
        int wincl = __popc(bal & (0xffffffffu >> (31 - lane)));
        if (lane == 31) wtot[w] = wincl;
        __syncthreads();
        if (w == 0) {
            int tv = wtot[lane];
            int x = tv;
            #pragma unroll
            for (int off = 1; off < 32; off <<= 1) {
                int y = __shfl_up_sync(0xffffffffu, x, off);
                if (lane >= off) x += y;
            }
            wbase[lane] = x - tv;
            if (lane == 31) wbase[32] = x;
        }
        __syncthreads();
        if (sel) {
            int pos = wbase[w] + wincl - 1;
            g_idx[b*N + pos]  = tid;
            g_invg[b*N + pos] = g_invn[b*N + tid];
        }
        if (tid == 0) {
            int M = wbase[32];
            g_M[b] = M;
            g_Mpad[b] = (M + 63) & ~63;
        }
    }
}

// ---------------- K3b: fused fg-proto + gather + bg-proto ----------------
__global__ void k_gfg(const float* __restrict__ q) {
    int bc = blockIdx.x;
    int b = bc / C;
    int t = threadIdx.x, lane = t & 31, w = t >> 5;
    __shared__ float sh[4];

    const float4* row4 = (const float4*)(q + (size_t)bc*N);
    const float4* wf4  = (const float4*)(g_wf + b*N);
    float s = 0.f;
    #pragma unroll
    for (int i = 0; i < 2; i++) {
        int p = t + i*128;
        float4 v = row4[p], wv = wf4[p];
        s += v.x*wv.x + v.y*wv.y + v.z*wv.z + v.w*wv.w;
    }
    s = warp_sum(s);
    if (lane == 0) sh[w] = s;
    __syncthreads();
    if (t == 0) g_fgp[bc] = (sh[0]+sh[1]+sh[2]+sh[3]) / g_wfsum[b];

    int Mb = g_M[b], Mpad = g_Mpad[b];
    const int* idx = g_idx + b*N;
    const float* row = q + (size_t)bc*N;
    float* vrow = g_Vg + (size_t)bc*N;
    float sb = 0.f;
    for (int m = t; m < Mb; m += 128) {       // row is L1-hot from the pass above
        float v = row[idx[m]];
        vrow[m] = v;
        sb += v;
    }
    for (int m = Mb + t; m < Mpad; m += 128) vrow[m] = 0.f;
    sb = warp_sum(sb);
    __syncthreads();
    if (lane == 0) sh[w] = sb;
    __syncthreads();
    if (t == 0) g_bgp[bc] = (sh[0]+sh[1]+sh[2]+sh[3]) / (float)Mb;
}

// ---------------- K5: S = exp(2 cn^T cn), double-buffered, 4 warps of 32x32 ----------------
__global__ __launch_bounds__(128) void k5_mma(const float* __restrict__ q) {
    int b  = blockIdx.z;
    int i0 = blockIdx.y * 64;
    int m0 = blockIdx.x * 64;
    int Mb = g_M[b];
    int Mpad = g_Mpad[b];
    if (m0 >= Mpad) return;

    __shared__ uint32_t As[2][32][72];
    __shared__ uint32_t Bs[2][32][72];

    int t = threadIdx.x;
    int lane = t & 31, w = t >> 5;
    int gid = lane >> 2, tig = lane & 3;
    int iw = (w >> 1) * 32;
    int mw = (w & 1) * 32;

    float acc[2][4][4] = {};

    const float* qb = q + (size_t)b*C*N;
    const float* vg = g_Vg + (size_t)b*C*N;

    int lr = t >> 4;              // 0..7
    int lc = (t & 15) * 4;        // 0..60

    float4 pa[4], pb[4];
    // prologue: load chunk 0
    #pragma unroll
    for (int rr = 0; rr < 4; rr++) {
        int k = lr + rr * 8;
        pa[rr] = *(const float4*)(qb + (size_t)k*N + i0 + lc);
        pb[rr] = *(const float4*)(vg + (size_t)k*N + m0 + lc);
    }
    #pragma unroll
    for (int rr = 0; rr < 4; rr++) {
        int k = lr + rr * 8;
        As[0][k][lc+0] = f2tf32(pa[rr].x); As[0][k][lc+1] = f2tf32(pa[rr].y);
        As[0][k][lc+2] = f2tf32(pa[rr].z); As[0][k][lc+3] = f2tf32(pa[rr].w);
        Bs[0][k][lc+0] = f2tf32(pb[rr].x); Bs[0][k][lc+1] = f2tf32(pb[rr].y);
        Bs[0][k][lc+2] = f2tf32(pb[rr].z); Bs[0][k][lc+3] = f2tf32(pb[rr].w);
    }
    __syncthreads();

    for (int c = 0; c < 16; c++) {
        int cur = c & 1, nxt = cur ^ 1;
        if (c + 1 < 16) {
            int k0 = (c + 1) * 32;
            #pragma unroll
            for (int rr = 0; rr < 4; rr++) {
                int k = k0 + lr + rr * 8;
                pa[rr] = *(const float4*)(qb + (size_t)k*N + i0 + lc);
                pb[rr] = *(const float4*)(vg + (size_t)k*N + m0 + lc);
            }
        }
        #pragma unroll
        for (int kk = 0; kk < 32; kk += 8) {
            uint32_t a[2][4];
            #pragma unroll
            for (int ti = 0; ti < 2; ti++) {
                a[ti][0] = As[cur][kk + tig    ][iw + ti*16 + gid];
                a[ti][1] = As[cur][kk + tig    ][iw + ti*16 + gid + 8];
                a[ti][2] = As[cur][kk + 4 + tig][iw + ti*16 + gid];
                a[ti][3] = As[cur][kk + 4 + tig][iw + ti*16 + gid + 8];
            }
            #pragma unroll
            for (int j = 0; j < 4; j++) {
                uint32_t b0 = Bs[cur][kk + tig    ][mw + 8*j + gid];
                uint32_t b1 = Bs[cur][kk + 4 + tig][mw + 8*j + gid];
                mma_tf32(acc[0][j], a[0][0], a[0][1], a[0][2], a[0][3], b0, b1);
                mma_tf32(acc[1][j], a[1][0], a[1][1], a[1][2], a[1][3], b0, b1);
            }
        }
        if (c + 1 < 16) {
            #pragma unroll
            for (int rr = 0; rr < 4; rr++) {
                int k = lr + rr * 8;
                As[nxt][k][lc+0] = f2tf32(pa[rr].x); As[nxt][k][lc+1] = f2tf32(pa[rr].y);
                As[nxt][k][lc+2] = f2tf32(pa[rr].z); As[nxt][k][lc+3] = f2tf32(pa[rr].w);
                Bs[nxt][k][lc+0] = f2tf32(pb[rr].x); Bs[nxt][k][lc+1] = f2tf32(pb[rr].y);
                Bs[nxt][k][lc+2] = f2tf32(pb[rr].z); Bs[nxt][k][lc+3] = f2tf32(pb[rr].w);
            }
            __syncthreads();
        }
    }

    #pragma unroll
    for (int ti = 0; ti < 2; ti++) {
        int ilo = i0 + iw + ti*16 + gid;
        int ihi = ilo + 8;
        float invlo = g_invn[b*N + ilo];
        float invhi = g_invn[b*N + ihi];
        float slo = 0.f, shi2 = 0.f;
        #pragma unroll
        for (int j = 0; j < 4; j++) {
            int m = m0 + mw + 8*j + 2*tig;
            bool in0 = m < Mb, in1 = (m + 1) < Mb;
            float ig0 = in0 ? g_invg[b*N + m]     : 0.f;
            float ig1 = in1 ? g_invg[b*N + m + 1] : 0.f;
            float e00 = in0 ? __expf(2.f * acc[ti][j][0] * invlo * ig0) : 0.f;
            float e01 = in1 ? __expf(2.f * acc[ti][j][1] * invlo * ig1) : 0.f;
            float e10 = in0 ? __expf(2.f * acc[ti][j][2] * invhi * ig0) : 0.f;
            float e11 = in1 ? __expf(2.f * acc[ti][j][3] * invhi * ig1) : 0.f;
            float* r0 = g_S + ((size_t)b*N + ilo)*N + m;
            float* r1 = g_S + ((size_t)b*N + ihi)*N + m;
            r0[0] = e00; r0[1] = e01;
            r1[0] = e10; r1[1] = e11;
            slo  += e00 + e01;
            shi2 += e10 + e11;
        }
        slo  += __shfl_xor_sync(0xffffffffu, slo, 1);
        slo  += __shfl_xor_sync(0xffffffffu, slo, 2);
        shi2 += __shfl_xor_sync(0xffffffffu, shi2, 1);
        shi2 += __shfl_xor_sync(0xffffffffu, shi2, 2);
        if (tig == 0) {
            atomicAdd(&g_denom[b*N + ilo], slo);
            atomicAdd(&g_denom[b*N + ihi], shi2);
        }
    }
}

// ---------------- K7: bg_local GEMM, double-buffered + fused FP1 + final partials ----------------
__global__ __launch_bounds__(128) void k7_mma(const float* __restrict__ q) {
    int b  = blockIdx.z;
    int c0 = blockIdx.y * 64;
    int i0 = blockIdx.x * 64;
    int Mpad = g_Mpad[b];

    __shared__ float sraw[9216];   // 36KB: As[2]/Bs[2] (4*64*36 u32); bp tile (64*65 f32) aliased
    #define K7_AS(u,r,c) (((uint32_t*)sraw)[(u)*2304 + (r)*36 + (c)])
    #define K7_BS(u,r,c) (((uint32_t*)sraw)[4608 + (u)*2304 + (r)*36 + (c)])
    #define K7_BP(r,c)   (sraw[(r)*65 + (c)])

    int t = threadIdx.x;
    int lane = t & 31, w = t >> 5;
    int gid = lane >> 2, tig = lane & 3;
    int cw = (w >> 1) * 32;
    int iw = (w & 1) * 32;

    float acc[2][4][4] = {};

    int lr = t >> 3;              // 0..15
    int lc = (t & 7) * 4;         // 0..28
    int nchunk = Mpad >> 5;

    float4 pa[4], pb[4];
    #pragma unroll
    for (int rr = 0; rr < 4; rr++) {
        int r = lr + rr * 16;
        pa[rr] = *(const float4*)(g_Vg + ((size_t)b*C + c0 + r)*N + lc);
        pb[rr] = *(const float4*)(g_S  + ((size_t)b*N + i0 + r)*N + lc);
    }
    #pragma unroll
    for (int rr = 0; rr < 4; rr++) {
        int r = lr + rr * 16;
        K7_AS(0,r,lc+0) = f2tf32(pa[rr].x); K7_AS(0,r,lc+1) = f2tf32(pa[rr].y);
        K7_AS(0,r,lc+2) = f2tf32(pa[rr].z); K7_AS(0,r,lc+3) = f2tf32(pa[rr].w);
        K7_BS(0,r,lc+0) = f2tf32(pb[rr].x); K7_BS(0,r,lc+1) = f2tf32(pb[rr].y);
        K7_BS(0,r,lc+2) = f2tf32(pb[rr].z); K7_BS(0,r,lc+3) = f2tf32(pb[rr].w);
    }
    __syncthreads();

    for (int c = 0; c < nchunk; c++) {
        int cur = c & 1, nxt = cur ^ 1;
        if (c + 1 < nchunk) {
            int m0 = (c + 1) * 32;
            #pragma unroll
            for (int rr = 0; rr < 4; rr++) {
                int r = lr + rr * 16;
                pa[rr] = *(const float4*)(g_Vg + ((size_t)b*C + c0 + r)*N + m0 + lc);
                pb[rr] = *(const float4*)(g_S  + ((size_t)b*N + i0 + r)*N + m0 + lc);
            }
        }
        #pragma unroll
        for (int kk = 0; kk < 32; kk += 8) {
            uint32_t a[2][4];
            #pragma unroll
            for (int tc = 0; tc < 2; tc++) {
                a[tc][0] = K7_AS(cur, cw + tc*16 + gid    , kk + tig);
                a[tc][1] = K7_AS(cur, cw + tc*16 + gid + 8, kk + tig);
                a[tc][2] = K7_AS(cur, cw + tc*16 + gid    , kk + 4 + tig);
                a[tc][3] = K7_AS(cur, cw + tc*16 + gid + 8, kk + 4 + tig);
            }
            #pragma unroll
            for (int j = 0; j < 4; j++) {
                uint32_t b0 = K7_BS(cur, iw + 8*j + gid, kk + tig);
                uint32_t b1 = K7_BS(cur, iw + 8*j + gid, kk + 4 + tig);
                mma_tf32(acc[0][j], a[0][0], a[0][1], a[0][2], a[0][3], b0, b1);
                mma_tf32(acc[1][j], a[1][0], a[1][1], a[1][2], a[1][3], b0, b1);
            }
        }
        if (c + 1 < nchunk) {
            #pragma unroll
            for (int rr = 0; rr < 4; rr++) {
                int r = lr + rr * 16;
                K7_AS(nxt,r,lc+0) = f2tf32(pa[rr].x); K7_AS(nxt,r,lc+1) = f2tf32(pa[rr].y);
                K7_AS(nxt,r,lc+2) = f2tf32(pa[rr].z); K7_AS(nxt,r,lc+3) = f2tf32(pa[rr].w);
                K7_BS(nxt,r,lc+0) = f2tf32(pb[rr].x); K7_BS(nxt,r,lc+1) = f2tf32(pb[rr].y);
                K7_BS(nxt,r,lc+2) = f2tf32(pb[rr].z); K7_BS(nxt,r,lc+3) = f2tf32(pb[rr].w);
            }
            __syncthreads();
        }
    }
    __syncthreads();   // all reads of As/Bs done before bp tile overwrites the alias

    // epilogue: bp tile into smem (bp = 0.3 bgp + 0.7 acc/denom)
    #pragma unroll
    for (int tc = 0; tc < 2; tc++) {
        int clo = c0 + cw + tc*16 + gid;
        float bglo = 0.3f * g_bgp[b*C + clo];
        float bghi = 0.3f * g_bgp[b*C + clo + 8];
        #pragma unroll
        for (int j = 0; j < 4; j++) {
            int i = iw + 8*j + 2*tig;
            float d0 = 0.7f / g_denom[b*N + i0 + i];
            float d1 = 0.7f / g_denom[b*N + i0 + i + 1];
            K7_BP(cw + tc*16 + gid    , i  ) = bglo + acc[tc][j][0] * d0;
            K7_BP(cw + tc*16 + gid    , i+1) = bglo + acc[tc][j][1] * d1;
            K7_BP(cw + tc*16 + gid + 8, i  ) = bghi + acc[tc][j][2] * d0;
            K7_BP(cw + tc*16 + gid + 8, i+1) = bghi + acc[tc][j][3] * d1;
        }
    }
    __syncthreads();

    // reduction: 2 threads per pixel, 32 channels each; FP1 computed on the fly
    int px = t >> 1;
    int cs = (t & 1) * 32;
    int i = i0 + px;
    const float* qcol = q + ((size_t)b*C + c0 + cs)*N + i;
    const float* fpv  = g_FP  + b*C + c0 + cs;
    const float* fgv  = g_fgp + b*C + c0 + cs;
    float sdf = 0.f, sdb = 0.f, sbb = 0.f;
    #pragma unroll
    for (int k = 0; k < 32; k++) {
        float qv = qcol[(size_t)k*N];
        float bp = K7_BP(cs + k, px);
        sdf += qv * (0.5f * (fpv[k] + fgv[k]));
        sdb += qv * bp;
        sbb += bp * bp;
    }
    sdf += __shfl_xor_sync(0xffffffffu, sdf, 1);
    sdb += __shfl_xor_sync(0xffffffffu, sdb, 1);
    sbb += __shfl_xor_sync(0xffffffffu, sbb, 1);
    if ((t & 1) == 0) {
        int cb = blockIdx.y;
        g_odf[cb][b*N + i] = sdf;
        g_odb[cb][b*N + i] = sdb;
        g_obb[cb][b*N + i] = sbb;
    }
    #undef K7_AS
    #undef K7_BS
    #undef K7_BP
}

// ---------------- K8: inline nFP1 + combine partials + write output ----------------
__global__ void k_out2(float* __restrict__ out) {
    __shared__ float sh[256];
    __shared__ float snF1;
    int t = threadIdx.x;
    int g = blockIdx.x * 256 + t;
    int b = g / N, n = g % N;
    float v0 = 0.5f * (g_FP[b*C + t]       + g_fgp[b*C + t]);
    float v1 = 0.5f * (g_FP[b*C + 256 + t] + g_fgp[b*C + 256 + t]);
    sh[t] = v0*v0 + v1*v1; __syncthreads();
    for (int off = 128; off > 0; off >>= 1) { if (t < off) sh[t] += sh[t+off]; __syncthreads(); }
    if (t == 0) snF1 = sqrtf(sh[0]);
    __syncthreads();

    float df = 0.f, db = 0.f, bb = 0.f;
    #pragma unroll
    for (int k = 0; k < OC; k++) {
        df += g_odf[k][g];
        db += g_odb[k][g];
        bb += g_obb[k][g];
    }
    float nq = g_qn[g];
    float nb = sqrtf(bb);
    out[(b*2 + 0)*N + n] = 10.f * db / fmaxf(nq * nb, 1e-8f);
    out[(b*2 + 1)*N + n] = 10.f * df / fmaxf(nq * snF1, 1e-8f);
}

// ---------------- launch ----------------
extern "C" void kernel_launch(void* const* d_in, const int* in_sizes, int n_in,
                              void* d_out, int out_size) {
    const float* q    = (const float*)d_in[0];
    const float* sf   = (const float*)d_in[1];
    const int*   mask = (const int*)d_in[2];
    float* out = (float*)d_out;

    k_pool   <<<B*C/8, 256>>>(sf, mask);
    k_pred1  <<<dim3(B*N/256, NCHP), 256>>>(q);
    k_pred2  <<<B*N/256, 256>>>();
    k_weights<<<dim3(2, B), 1024>>>();
    k_gfg    <<<B*C, 128>>>(q);
    k5_mma   <<<dim3(N/64, N/64, B), 128>>>(q);
    k7_mma   <<<dim3(N/64, C/64, B), 128>>>(q);
    k_out2   <<<B*N/256, 256>>>(out);
}

// round 13
// speedup vs baseline: 1.2541x; 1.0115x over previous
#include <cuda_runtime.h>
#include <math.h>
#include <stdint.h>

#define B 8
#define C 512
#define N 1024
#define TOPK 12
#define NCHP 16
#define PC (C/NCHP)     // 32 channels per pred chunk
#define OC 4            // output c-blocks (C/128)

// ---------------- device scratch (no allocations allowed) ----------------
__device__ float g_FP[B*C], g_BP[B*C];
__device__ float g_invn[B*N], g_qn[B*N];
__device__ float g_wf[B*N];
__device__ float g_wfsum[B];
__device__ int   g_idx[B*N];
__device__ int   g_M[B];
__device__ int   g_Mpad[B];
__device__ float g_invg[B*N];
__device__ float g_Vg[(size_t)B*C*N];        // gathered active columns (zero-padded to Mpad)
__device__ float g_S[(size_t)B*N*N];         // exp scores (N x Mpad per batch, zero beyond Mb)
__device__ float g_denom[B*N];
__device__ float g_fgp[B*C], g_bgp[B*C];

// split partials
__device__ float g_pdf[NCHP][B*N], g_pdb[NCHP][B*N], g_pqq[NCHP][B*N];
__device__ float g_odf[OC][B*N], g_odb[OC][B*N], g_obb[OC][B*N];

// ---------------- helpers ----------------
__device__ __forceinline__ float warp_sum(float v) {
    #pragma unroll
    for (int off = 16; off > 0; off >>= 1) v += __shfl_down_sync(0xffffffffu, v, off);
    return v;
}

__device__ __forceinline__ uint32_t f2tf32(float f) {
    uint32_t u;
    asm("cvt.rna.tf32.f32 %0, %1;" : "=r"(u) : "f"(f));
    return u;
}

__device__ __forceinline__ void mma_tf32(float c[4],
                                         uint32_t a0, uint32_t a1, uint32_t a2, uint32_t a3,
                                         uint32_t b0, uint32_t b1) {
    asm volatile("mma.sync.aligned.m16n8k8.row.col.f32.tf32.tf32.f32 "
                 "{%0,%1,%2,%3}, {%4,%5,%6,%7}, {%8,%9}, {%0,%1,%2,%3};"
                 : "+f"(c[0]), "+f"(c[1]), "+f"(c[2]), "+f"(c[3])
                 : "r"(a0), "r"(a1), "r"(a2), "r"(a3), "r"(b0), "r"(b1));
}

// ---------------- K1: masked avg pool (FP/BP) + inline counts, one warp per (b,c) ----------------
__global__ void k_pool(const float* __restrict__ sf, const int* __restrict__ mask) {
    int w = blockIdx.x * 8 + (threadIdx.x >> 5);
    int lane = threadIdx.x & 31;
    int b = w / C, c = w % C;
    const float4* row4 = (const float4*)(sf + (size_t)w*N);
    const int4*   m4   = (const int4*)(mask + b*N);
    float s1 = 0.f, s0 = 0.f, c1 = 0.f;
    #pragma unroll
    for (int i = 0; i < 8; i++) {
        int p = lane + i*32;
        float4 v = row4[p];
        int4 mk = m4[p];
        float fx = (float)mk.x, fy = (float)mk.y, fz = (float)mk.z, fw = (float)mk.w;
        s1 += fx*v.x + fy*v.y + fz*v.z + fw*v.w;
        s0 += (1.f-fx)*v.x + (1.f-fy)*v.y + (1.f-fz)*v.z + (1.f-fw)*v.w;
        c1 += fx + fy + fz + fw;
    }
    s1 = warp_sum(s1); s0 = warp_sum(s0); c1 = warp_sum(c1);
    if (lane == 0) {
        g_FP[b*C + c] = s1 / (c1 + 1e-5f);
        g_BP[b*C + c] = s0 / ((float)N - c1 + 1e-5f);
    }
}

// ---------------- K2a: split-C partial dot products for pred ----------------
__global__ __launch_bounds__(256) void k_pred1(const float* __restrict__ q) {
    int g = blockIdx.x * blockDim.x + threadIdx.x;   // pixel id (b*N+n)
    int chunk = blockIdx.y;
    int b = g / N, n = g % N;
    const float* qb = q + (size_t)b*C*N + (size_t)chunk*PC*N + n;
    const float* fp = g_FP + b*C + chunk*PC;
    const float* bp = g_BP + b*C + chunk*PC;
    float df = 0.f, db = 0.f, qq = 0.f;
    #pragma unroll 16
    for (int c = 0; c < PC; c++) {
        float v = qb[(size_t)c*N];
        df += v * fp[c];
        db += v * bp[c];
        qq += v * v;
    }
    g_pdf[chunk][g] = df;
    g_pdb[chunk][g] = db;
    g_pqq[chunk][g] = qq;
}

// ---------------- K2b: fused norms + pred softmax + fg/bg selection (1 block/batch) ----------------
__global__ __launch_bounds__(1024) void k_predw() {
    int b = blockIdx.x;
    int t = threadIdx.x;
    int lane = t & 31, w = t >> 5;
    __shared__ float sh[512];
    __shared__ float snF_s, snB_s;

    if (t < 512) { float a = g_FP[b*C + t]; sh[t] = a*a; }
    __syncthreads();
    for (int off = 256; off > 0; off >>= 1) { if (t < off) sh[t] += sh[t+off]; __syncthreads(); }
    if (t == 0) snF_s = sqrtf(sh[0]);
    __syncthreads();
    if (t < 512) { float a = g_BP[b*C + t]; sh[t] = a*a; }
    __syncthreads();
    for (int off = 256; off > 0; off >>= 1) { if (t < off) sh[t] += sh[t+off]; __syncthreads(); }
    if (t == 0) snB_s = sqrtf(sh[0]);
    __syncthreads();

    int g = b*N + t;
    float df = 0.f, db = 0.f, qq = 0.f;
    #pragma unroll
    for (int k = 0; k < NCHP; k++) {
        df += g_pdf[k][g];
        db += g_pdb[k][g];
        qq += g_pqq[k][g];
    }
    float nq = sqrtf(qq);
    float sf = 10.f * df / fmaxf(nq * snF_s, 1e-8f);
    float sb = 10.f * db / fmaxf(nq * snB_s, 1e-8f);
    float mx = fmaxf(sf, sb);
    float ef = expf(sf - mx), eb = expf(sb - mx);
    float inv = 1.f / (ef + eb);
    float pfg = ef * inv;
    float pbg = eb * inv;
    float invn = 1.f / fmaxf(nq, 1e-20f);
    g_qn[g] = nq;
    g_invn[g] = invn;
    g_denom[g] = 0.f;

    __shared__ float shv[32];
    __shared__ int   shi[32];
    __shared__ int   swin;
    __shared__ int   wtot[32];
    __shared__ int   wbase[33];

    for (int which = 0; which < 2; which++) {
        float p = which ? pbg : pfg;
        float thres = which ? 0.6f : 0.7f;
        int flag = (p > thres) ? 1 : 0;
        int cnt = __syncthreads_count(flag);
        bool sel;
        if (cnt > 0) {
            sel = (flag != 0);
        } else {
            bool taken = false;
            for (int it = 0; it < TOPK; it++) {
                float v = taken ? -1e30f : p;
                int id = t;
                #pragma unroll
                for (int off = 16; off > 0; off >>= 1) {
                    float ov = __shfl_down_sync(0xffffffffu, v, off);
                    int   oi = __shfl_down_sync(0xffffffffu, id, off);
                    if (ov > v || (ov == v && oi < id)) { v = ov; id = oi; }
                }
                if (lane == 0) { shv[w] = v; shi[w] = id; }
                __syncthreads();
                if (w == 0) {
                    float v2 = shv[lane]; int i2 = shi[lane];
                    #pragma unroll
                    for (int off = 16; off > 0; off >>= 1) {
                        float ov = __shfl_down_sync(0xffffffffu, v2, off);
                        int   oi = __shfl_down_sync(0xffffffffu, i2, off);
                        if (ov > v2 || (ov == v2 && oi < i2)) { v2 = ov; i2 = oi; }
                    }
                    if (lane == 0) swin = i2;
                }
                __syncthreads();
                if (t == swin) taken = true;
            }
            sel = taken;
        }
        float wsum = (cnt > 0) ? (float)cnt : (float)TOPK;
        if (which == 0) {
            g_wf[g] = sel ? 1.f : 0.f;
            if (t == 0) g_wfsum[b] = wsum;
        } else {
            unsigned bal = __ballot_sync(0xffffffffu, sel);
            int wincl = __popc(bal & (0xffffffffu >> (31 - lane)));
            if (lane == 31) wtot[w] = wincl;
            __syncthreads();
            if (w == 0) {
                int tv = wtot[lane];
                int x = tv;
                #pragma unroll
                for (int off = 1; off < 32; off <<= 1) {
                    int y = __shfl_up_sync(0xffffffffu, x, off);
                    if (lane >= off) x += y;
                }
                wbase[lane] = x - tv;
                if (lane == 31) wbase[32] = x;
            }
            __syncthreads();
            if (sel) {
                int pos = wbase[w] + wincl - 1;
                g_idx[b*N + pos]  = t;
                g_invg[b*N + pos] = invn;
            }
            if (t == 0) {
                int M = wbase[32];
                g_M[b] = M;
                g_Mpad[b] = (M + 63) & ~63;
            }
        }
        __syncthreads();
    }
}

// ---------------- K3b: fused fg-proto + gather + bg-proto ----------------
__global__ void k_gfg(const float* __restrict__ q) {
    int bc = blockIdx.x;
    int b = bc / C;
    int t = threadIdx.x, lane = t & 31, w = t >> 5;
    __shared__ float sh[4];

    const float4* row4 = (const float4*)(q + (size_t)bc*N);
    const float4* wf4  = (const float4*)(g_wf + b*N);
    float s = 0.f;
    #pragma unroll
    for (int i = 0; i < 2; i++) {
        int p = t + i*128;
        float4 v = row4[p], wv = wf4[p];
        s += v.x*wv.x + v.y*wv.y + v.z*wv.z + v.w*wv.w;
    }
    s = warp_sum(s);
    if (lane == 0) sh[w] = s;
    __syncthreads();
    if (t == 0) g_fgp[bc] = (sh[0]+sh[1]+sh[2]+sh[3]) / g_wfsum[b];

    int Mb = g_M[b], Mpad = g_Mpad[b];
    const int* idx = g_idx + b*N;
    const float* row = q + (size_t)bc*N;
    float* vrow = g_Vg + (size_t)bc*N;
    float sb = 0.f;
    for (int m = t; m < Mb; m += 128) {       // row is L1-hot from the pass above
        float v = row[idx[m]];
        vrow[m] = v;
        sb += v;
    }
    for (int m = Mb + t; m < Mpad; m += 128) vrow[m] = 0.f;
    sb = warp_sum(sb);
    __syncthreads();
    if (lane == 0) sh[w] = sb;
    __syncthreads();
    if (t == 0) g_bgp[bc] = (sh[0]+sh[1]+sh[2]+sh[3]) / (float)Mb;
}

// ---------------- K5: S = exp(2 cn^T cn), 128(i)x64(m) tiles, double-buffered ----------------
// smem: As[2][32][136] (q tile, k x i), Bs[2][32][72] (Vg tile, k x m) -> 53,248 B dynamic
#define AS5(u,r,c) s5[(size_t)(u)*32*136 + (r)*136 + (c)]
#define BS5(u,r,c) s5[2*32*136 + (size_t)(u)*32*72 + (r)*72 + (c)]
__global__ __launch_bounds__(256) void k5_mma(const float* __restrict__ q) {
    extern __shared__ uint32_t s5[];
    int b  = blockIdx.z;
    int i0 = blockIdx.y * 128;
    int m0 = blockIdx.x * 64;
    int Mb = g_M[b];
    int Mpad = g_Mpad[b];
    if (m0 >= Mpad) return;

    int t = threadIdx.x;
    int lane = t & 31, w = t >> 5;
    int gid = lane >> 2, tig = lane & 3;
    int iw = (w >> 1) * 32;       // 0..96 within 128-i tile
    int mw = (w & 1) * 32;

    float acc[2][4][4] = {};

    const float* qb = q + (size_t)b*C*N;
    const float* vg = g_Vg + (size_t)b*C*N;

    int lrA = t >> 5;             // 0..7
    int lcA = (t & 31) * 4;       // 0..124
    int lrB = t >> 4;             // 0..15
    int lcB = (t & 15) * 4;       // 0..60

    float4 pa[4], pb[2];
    #pragma unroll
    for (int rr = 0; rr < 4; rr++)
        pa[rr] = *(const float4*)(qb + (size_t)(lrA + rr*8)*N + i0 + lcA);
    #pragma unroll
    for (int rr = 0; rr < 2; rr++)
        pb[rr] = *(const float4*)(vg + (size_t)(lrB + rr*16)*N + m0 + lcB);
    #pragma unroll
    for (int rr = 0; rr < 4; rr++) {
        int k = lrA + rr*8;
        AS5(0,k,lcA+0) = f2tf32(pa[rr].x); AS5(0,k,lcA+1) = f2tf32(pa[rr].y);
        AS5(0,k,lcA+2) = f2tf32(pa[rr].z); AS5(0,k,lcA+3) = f2tf32(pa[rr].w);
    }
    #pragma unroll
    for (int rr = 0; rr < 2; rr++) {
        int k = lrB + rr*16;
        BS5(0,k,lcB+0) = f2tf32(pb[rr].x); BS5(0,k,lcB+1) = f2tf32(pb[rr].y);
        BS5(0,k,lcB+2) = f2tf32(pb[rr].z); BS5(0,k,lcB+3) = f2tf32(pb[rr].w);
    }
    __syncthreads();

    for (int c = 0; c < 16; c++) {
        int cur = c & 1, nxt = cur ^ 1;
        if (c + 1 < 16) {
            int k0 = (c + 1) * 32;
            #pragma unroll
            for (int rr = 0; rr < 4; rr++)
                pa[rr] = *(const float4*)(qb + (size_t)(k0 + lrA + rr*8)*N + i0 + lcA);
            #pragma unroll
            for (int rr = 0; rr < 2; rr++)
                pb[rr] = *(const float4*)(vg + (size_t)(k0 + lrB + rr*16)*N + m0 + lcB);
        }
        #pragma unroll
        for (int kk = 0; kk < 32; kk += 8) {
            uint32_t a[2][4];
            #pragma unroll
            for (int ti = 0; ti < 2; ti++) {
                a[ti][0] = AS5(cur, kk + tig    , iw + ti*16 + gid);
                a[ti][1] = AS5(cur, kk + tig    , iw + ti*16 + gid + 8);
                a[ti][2] = AS5(cur, kk + 4 + tig, iw + ti*16 + gid);
                a[ti][3] = AS5(cur, kk + 4 + tig, iw + ti*16 + gid + 8);
            }
            #pragma unroll
            for (int j = 0; j < 4; j++) {
                uint32_t b0 = BS5(cur, kk + tig    , mw + 8*j + gid);
                uint32_t b1 = BS5(cur, kk + 4 + tig, mw + 8*j + gid);
                mma_tf32(acc[0][j], a[0][0], a[0][1], a[0][2], a[0][3], b0, b1);
                mma_tf32(acc[1][j], a[1][0], a[1][1], a[1][2], a[1][3], b0, b1);
            }
        }
        if (c + 1 < 16) {
            #pragma unroll
            for (int rr = 0; rr < 4; rr++) {
                int k = lrA + rr*8;
                AS5(nxt,k,lcA+0) = f2tf32(pa[rr].x); AS5(nxt,k,lcA+1) = f2tf32(pa[rr].y);
                AS5(nxt,k,lcA+2) = f2tf32(pa[rr].z); AS5(nxt,k,lcA+3) = f2tf32(pa[rr].w);
            }
            #pragma unroll
            for (int rr = 0; rr < 2; rr++) {
                int k = lrB + rr*16;
                BS5(nxt,k,lcB+0) = f2tf32(pb[rr].x); BS5(nxt,k,lcB+1) = f2tf32(pb[rr].y);
                BS5(nxt,k,lcB+2) = f2tf32(pb[rr].z); BS5(nxt,k,lcB+3) = f2tf32(pb[rr].w);
            }
            __syncthreads();
        }
    }

    #pragma unroll
    for (int ti = 0; ti < 2; ti++) {
        int ilo = i0 + iw + ti*16 + gid;
        int ihi = ilo + 8;
        float invlo = g_invn[b*N + ilo];
        float invhi = g_invn[b*N + ihi];
        float slo = 0.f, shi2 = 0.f;
        #pragma unroll
        for (int j = 0; j < 4; j++) {
            int m = m0 + mw + 8*j + 2*tig;
            bool in0 = m < Mb, in1 = (m + 1) < Mb;
            float ig0 = in0 ? g_invg[b*N + m]     : 0.f;
            float ig1 = in1 ? g_invg[b*N + m + 1] : 0.f;
            float e00 = in0 ? __expf(2.f * acc[ti][j][0] * invlo * ig0) : 0.f;
            float e01 = in1 ? __expf(2.f * acc[ti][j][1] * invlo * ig1) : 0.f;
            float e10 = in0 ? __expf(2.f * acc[ti][j][2] * invhi * ig0) : 0.f;
            float e11 = in1 ? __expf(2.f * acc[ti][j][3] * invhi * ig1) : 0.f;
            float* r0 = g_S + ((size_t)b*N + ilo)*N + m;
            float* r1 = g_S + ((size_t)b*N + ihi)*N + m;
            r0[0] = e00; r0[1] = e01;
            r1[0] = e10; r1[1] = e11;
            slo  += e00 + e01;
            shi2 += e10 + e11;
        }
        slo  += __shfl_xor_sync(0xffffffffu, slo, 1);
        slo  += __shfl_xor_sync(0xffffffffu, slo, 2);
        shi2 += __shfl_xor_sync(0xffffffffu, shi2, 1);
        shi2 += __shfl_xor_sync(0xffffffffu, shi2, 2);
        if (tig == 0) {
            atomicAdd(&g_denom[b*N + ilo], slo);
            atomicAdd(&g_denom[b*N + ihi], shi2);
        }
    }
}

// ---------------- K7: bg_local GEMM, 128(c)x64(i) tiles, double-buffered + fused epilogue ----------------
// smem: As[2][128][36] (Vg), Bs[2][64][36] (S) -> 55,296 B dynamic; bp tile 128x65 aliased
#define AS7(u,r,c) (((uint32_t*)s7)[(size_t)(u)*128*36 + (r)*36 + (c)])
#define BS7(u,r,c) (((uint32_t*)s7)[2*128*36 + (size_t)(u)*64*36 + (r)*36 + (c)])
#define BP7(r,c)   (s7[(r)*65 + (c)])
__global__ __launch_bounds__(256) void k7_mma(const float* __restrict__ q) {
    extern __shared__ float s7[];
    int b  = blockIdx.z;
    int c0 = blockIdx.y * 128;
    int i0 = blockIdx.x * 64;
    int Mpad = g_Mpad[b];

    int t = threadIdx.x;
    int lane = t & 31, w = t >> 5;
    int gid = lane >> 2, tig = lane & 3;
    int cw = (w >> 1) * 32;       // 0..96 within 128-c tile
    int iw = (w & 1) * 32;

    float acc[2][4][4] = {};

    int lr = t >> 3;              // 0..31
    int lc = (t & 7) * 4;         // 0..28
    int nchunk = Mpad >> 5;

    float4 pa[4], pb[2];
    #pragma unroll
    for (int rr = 0; rr < 4; rr++)
        pa[rr] = *(const float4*)(g_Vg + ((size_t)b*C + c0 + lr + rr*32)*N + lc);
    #pragma unroll
    for (int rr = 0; rr < 2; rr++)
        pb[rr] = *(const float4*)(g_S  + ((size_t)b*N + i0 + lr + rr*32)*N + lc);
    #pragma unroll
    for (int rr = 0; rr < 4; rr++) {
        int r = lr + rr*32;
        AS7(0,r,lc+0) = f2tf32(pa[rr].x); AS7(0,r,lc+1) = f2tf32(pa[rr].y);
        AS7(0,r,lc+2) = f2tf32(pa[rr].z); AS7(0,r,lc+3) = f2tf32(pa[rr].w);
    }
    #pragma unroll
    for (int rr = 0; rr < 2; rr++) {
        int r = lr + rr*32;
        BS7(0,r,lc+0) = f2tf32(pb[rr].x); BS7(0,r,lc+1) = f2tf32(pb[rr].y);
        BS7(0,r,lc+2) = f2tf32(pb[rr].z); BS7(0,r,lc+3) = f2tf32(pb[rr].w);
    }
    __syncthreads();

    for (int c = 0; c < nchunk; c++) {
        int cur = c & 1, nxt = cur ^ 1;
        if (c + 1 < nchunk) {
            int m0 = (c + 1) * 32;
            #pragma unroll
            for (int rr = 0; rr < 4; rr++)
                pa[rr] = *(const float4*)(g_Vg + ((size_t)b*C + c0 + lr + rr*32)*N + m0 + lc);
            #pragma unroll
            for (int rr = 0; rr < 2; rr++)
                pb[rr] = *(const float4*)(g_S  + ((size_t)b*N + i0 + lr + rr*32)*N + m0 + lc);
        }
        #pragma unroll
        for (int kk = 0; kk < 32; kk += 8) {
            uint32_t a[2][4];
            #pragma unroll
            for (int tc = 0; tc < 2; tc++) {
                a[tc][0] = AS7(cur, cw + tc*16 + gid    , kk + tig);
                a[tc][1] = AS7(cur, cw + tc*16 + gid + 8, kk + tig);
                a[tc][2] = AS7(cur, cw + tc*16 + gid    , kk + 4 + tig);
                a[tc][3] = AS7(cur, cw + tc*16 + gid + 8, kk + 4 + tig);
            }
            #pragma unroll
            for (int j = 0; j < 4; j++) {
                uint32_t b0 = BS7(cur, iw + 8*j + gid, kk + tig);
                uint32_t b1 = BS7(cur, iw + 8*j + gid, kk + 4 + tig);
                mma_tf32(acc[0][j], a[0][0], a[0][1], a[0][2], a[0][3], b0, b1);
                mma_tf32(acc[1][j], a[1][0], a[1][1], a[1][2], a[1][3], b0, b1);
            }
        }
        if (c + 1 < nchunk) {
            #pragma unroll
            for (int rr = 0; rr < 4; rr++) {
                int r = lr + rr*32;
                AS7(nxt,r,lc+0) = f2tf32(pa[rr].x); AS7(nxt,r,lc+1) = f2tf32(pa[rr].y);
                AS7(nxt,r,lc+2) = f2tf32(pa[rr].z); AS7(nxt,r,lc+3) = f2tf32(pa[rr].w);
            }
            #pragma unroll
            for (int rr = 0; rr < 2; rr++) {
                int r = lr + rr*32;
                BS7(nxt,r,lc+0) = f2tf32(pb[rr].x); BS7(nxt,r,lc+1) = f2tf32(pb[rr].y);
                BS7(nxt,r,lc+2) = f2tf32(pb[rr].z); BS7(nxt,r,lc+3) = f2tf32(pb[rr].w);
            }
            __syncthreads();
        }
    }
    __syncthreads();   // all frag reads done before bp tile overwrites the alias

    // epilogue: bp tile into smem (bp = 0.3 bgp + 0.7 acc/denom)
    #pragma unroll
    for (int tc = 0; tc < 2; tc++) {
        int clo = c0 + cw + tc*16 + gid;
        float bglo = 0.3f * g_bgp[b*C + clo];
        float bghi = 0.3f * g_bgp[b*C + clo + 8];
        #pragma unroll
        for (int j = 0; j < 4; j++) {
            int i = iw + 8*j + 2*tig;
            float d0 = 0.7f / g_denom[b*N + i0 + i];
            float d1 = 0.7f / g_denom[b*N + i0 + i + 1];
            BP7(cw + tc*16 + gid    , i  ) = bglo + acc[tc][j][0] * d0;
            BP7(cw + tc*16 + gid    , i+1) = bglo + acc[tc][j][1] * d1;
            BP7(cw + tc*16 + gid + 8, i  ) = bghi + acc[tc][j][2] * d0;
            BP7(cw + tc*16 + gid + 8, i+1) = bghi + acc[tc][j][3] * d1;
        }
    }
    __syncthreads();

    // reduction: 4 threads per pixel, 32 channels each, bank-conflict-free via k-rotation
    int px = t >> 2;              // 0..63
    int cs = (t & 3) * 32;        // 0,32,64,96
    int rot = (t & 3) * 8;
    int i = i0 + px;
    const float* qcol = q + ((size_t)b*C + c0 + cs)*N + i;
    const float* fpv  = g_FP  + b*C + c0 + cs;
    const float* fgv  = g_fgp + b*C + c0 + cs;
    float sdf = 0.f, sdb = 0.f, sbb = 0.f;
    #pragma unroll
    for (int k = 0; k < 32; k++) {
        int kr = (k + rot) & 31;
        float qv = qcol[(size_t)kr*N];
        float bp = BP7(cs + kr, px);
        sdf += qv * (0.5f * (fpv[kr] + fgv[kr]));
        sdb += qv * bp;
        sbb += bp * bp;
    }
    sdf += __shfl_xor_sync(0xffffffffu, sdf, 1);
    sdf += __shfl_xor_sync(0xffffffffu, sdf, 2);
    sdb += __shfl_xor_sync(0xffffffffu, sdb, 1);
    sdb += __shfl_xor_sync(0xffffffffu, sdb, 2);
    sbb += __shfl_xor_sync(0xffffffffu, sbb, 1);
    sbb += __shfl_xor_sync(0xffffffffu, sbb, 2);
    if ((t & 3) == 0) {
        int cb = blockIdx.y;
        g_odf[cb][b*N + i] = sdf;
        g_odb[cb][b*N + i] = sdb;
        g_obb[cb][b*N + i] = sbb;
    }
}

// ---------------- K8: inline nFP1 + combine partials + write output ----------------
__global__ void k_out2(float* __restrict__ out) {
    __shared__ float sh[256];
    __shared__ float snF1;
    int t = threadIdx.x;
    int g = blockIdx.x * 256 + t;
    int b = g / N, n = g % N;
    float v0 = 0.5f * (g_FP[b*C + t]       + g_fgp[b*C + t]);
    float v1 = 0.5f * (g_FP[b*C + 256 + t] + g_fgp[b*C + 256 + t]);
    sh[t] = v0*v0 + v1*v1; __syncthreads();
    for (int off = 128; off > 0; off >>= 1) { if (t < off) sh[t] += sh[t+off]; __syncthreads(); }
    if (t == 0) snF1 = sqrtf(sh[0]);
    __syncthreads();

    float df = 0.f, db = 0.f, bb = 0.f;
    #pragma unroll
    for (int k = 0; k < OC; k++) {
        df += g_odf[k][g];
        db += g_odb[k][g];
        bb += g_obb[k][g];
    }
    float nq = g_qn[g];
    float nb = sqrtf(bb);
    out[(b*2 + 0)*N + n] = 10.f * db / fmaxf(nq * nb, 1e-8f);
    out[(b*2 + 1)*N + n] = 10.f * df / fmaxf(nq * snF1, 1e-8f);
}

// ---------------- launch ----------------
extern "C" void kernel_launch(void* const* d_in, const int* in_sizes, int n_in,
                              void* d_out, int out_size) {
    const float* q    = (const float*)d_in[0];
    const float* sf   = (const float*)d_in[1];
    const int*   mask = (const int*)d_in[2];
    float* out = (float*)d_out;

    const int SMEM5 = (2*32*136 + 2*32*72) * 4;   // 53,248 B
    const int SMEM7 = (2*128*36 + 2*64*36) * 4;   // 55,296 B
    cudaFuncSetAttribute(k5_mma, cudaFuncAttributeMaxDynamicSharedMemorySize, SMEM5);
    cudaFuncSetAttribute(k7_mma, cudaFuncAttributeMaxDynamicSharedMemorySize, SMEM7);

    k_pool  <<<B*C/8, 256>>>(sf, mask);
    k_pred1 <<<dim3(B*N/256, NCHP), 256>>>(q);
    k_predw <<<B, 1024>>>();
    k_gfg   <<<B*C, 128>>>(q);
    k5_mma  <<<dim3(N/64, N/128, B), 256, SMEM5>>>(q);
    k7_mma  <<<dim3(N/64, C/128, B), 256, SMEM7>>>(q);
    k_out2  <<<B*N/256, 256>>>(out);
}

// round 14
// speedup vs baseline: 1.2875x; 1.0266x over previous
#include <cuda_runtime.h>
#include <math.h>
#include <stdint.h>

#define B 8
#define C 512
#define N 1024
#define TOPK 12
#define NCHP 32
#define PC (C/NCHP)     // 16 channels per pred chunk
#define OC 4            // output c-blocks (C/128)

// ---------------- device scratch (no allocations allowed) ----------------
__device__ float g_FP[B*C], g_BP[B*C];
__device__ float g_invn[B*N], g_qn[B*N];
__device__ float g_wf[B*N];
__device__ float g_wfsum[B];
__device__ int   g_idx[B*N];
__device__ int   g_M[B];
__device__ int   g_Mpad[B];
__device__ float g_invg[B*N];
__device__ float g_Vg[(size_t)B*C*N];        // gathered active columns (zero-padded to Mpad)
__device__ float g_S[(size_t)B*N*N];         // exp scores (N x Mpad per batch, zero beyond Mb)
__device__ float g_denom[B*N];
__device__ float g_fgp[B*C], g_bgp[B*C];

// split partials
__device__ float g_pdf[NCHP][B*N], g_pdb[NCHP][B*N], g_pqq[NCHP][B*N];
__device__ float g_odf[OC][B*N], g_odb[OC][B*N], g_obb[OC][B*N];

// ---------------- helpers ----------------
__device__ __forceinline__ float warp_sum(float v) {
    #pragma unroll
    for (int off = 16; off > 0; off >>= 1) v += __shfl_down_sync(0xffffffffu, v, off);
    return v;
}

__device__ __forceinline__ uint32_t f2tf32(float f) {
    uint32_t u;
    asm("cvt.rna.tf32.f32 %0, %1;" : "=r"(u) : "f"(f));
    return u;
}

__device__ __forceinline__ void mma_tf32(float c[4],
                                         uint32_t a0, uint32_t a1, uint32_t a2, uint32_t a3,
                                         uint32_t b0, uint32_t b1) {
    asm volatile("mma.sync.aligned.m16n8k8.row.col.f32.tf32.tf32.f32 "
                 "{%0,%1,%2,%3}, {%4,%5,%6,%7}, {%8,%9}, {%0,%1,%2,%3};"
                 : "+f"(c[0]), "+f"(c[1]), "+f"(c[2]), "+f"(c[3])
                 : "r"(a0), "r"(a1), "r"(a2), "r"(a3), "r"(b0), "r"(b1));
}

// ---------------- K1: masked avg pool (FP/BP) + inline counts, one warp per (b,c) ----------------
__global__ void k_pool(const float* __restrict__ sf, const int* __restrict__ mask) {
    int w = blockIdx.x * 8 + (threadIdx.x >> 5);
    int lane = threadIdx.x & 31;
    int b = w / C, c = w % C;
    const float4* row4 = (const float4*)(sf + (size_t)w*N);
    const int4*   m4   = (const int4*)(mask + b*N);
    float s1 = 0.f, s0 = 0.f, c1 = 0.f;
    #pragma unroll
    for (int i = 0; i < 8; i++) {
        int p = lane + i*32;
        float4 v = row4[p];
        int4 mk = m4[p];
        float fx = (float)mk.x, fy = (float)mk.y, fz = (float)mk.z, fw = (float)mk.w;
        s1 += fx*v.x + fy*v.y + fz*v.z + fw*v.w;
        s0 += (1.f-fx)*v.x + (1.f-fy)*v.y + (1.f-fz)*v.z + (1.f-fw)*v.w;
        c1 += fx + fy + fz + fw;
    }
    s1 = warp_sum(s1); s0 = warp_sum(s0); c1 = warp_sum(c1);
    if (lane == 0) {
        g_FP[b*C + c] = s1 / (c1 + 1e-5f);
        g_BP[b*C + c] = s0 / ((float)N - c1 + 1e-5f);
    }
}

// ---------------- K2a: split-C partial dots, 2 pixels/thread (float2), PC=16 ----------------
__global__ __launch_bounds__(256) void k_pred1(const float* __restrict__ q) {
    int t = threadIdx.x;
    int g2 = blockIdx.x * 256 + t;          // pixel-pair id (B*N/2 total)
    int chunk = blockIdx.y;
    int b = g2 >> 9;                        // 512 pairs per batch
    int n = (g2 & 511) * 2;
    const float* qb = q + (size_t)b*C*N + (size_t)chunk*PC*N + n;
    const float* fp = g_FP + b*C + chunk*PC;
    const float* bp = g_BP + b*C + chunk*PC;
    float2 df = {0,0}, db = {0,0}, qq = {0,0};
    #pragma unroll
    for (int c = 0; c < PC; c++) {
        float2 v = *(const float2*)(qb + (size_t)c*N);
        float f = fp[c], p = bp[c];
        df.x += v.x*f; df.y += v.y*f;
        db.x += v.x*p; db.y += v.y*p;
        qq.x += v.x*v.x; qq.y += v.y*v.y;
    }
    int g = b*N + n;
    *(float2*)&g_pdf[chunk][g] = df;
    *(float2*)&g_pdb[chunk][g] = db;
    *(float2*)&g_pqq[chunk][g] = qq;
}

// ---------------- K2b: fused norms + pred softmax + fg/bg selection (1 block/batch) ----------------
__global__ __launch_bounds__(1024) void k_predw() {
    int b = blockIdx.x;
    int t = threadIdx.x;
    int lane = t & 31, w = t >> 5;
    __shared__ float sh[512];
    __shared__ float snF_s, snB_s;

    if (t < 512) { float a = g_FP[b*C + t]; sh[t] = a*a; }
    __syncthreads();
    for (int off = 256; off > 0; off >>= 1) { if (t < off) sh[t] += sh[t+off]; __syncthreads(); }
    if (t == 0) snF_s = sqrtf(sh[0]);
    __syncthreads();
    if (t < 512) { float a = g_BP[b*C + t]; sh[t] = a*a; }
    __syncthreads();
    for (int off = 256; off > 0; off >>= 1) { if (t < off) sh[t] += sh[t+off]; __syncthreads(); }
    if (t == 0) snB_s = sqrtf(sh[0]);
    __syncthreads();

    int g = b*N + t;
    float df = 0.f, db = 0.f, qq = 0.f;
    #pragma unroll
    for (int k = 0; k < NCHP; k++) {
        df += g_pdf[k][g];
        db += g_pdb[k][g];
        qq += g_pqq[k][g];
    }
    float nq = sqrtf(qq);
    float sf = 10.f * df / fmaxf(nq * snF_s, 1e-8f);
    float sb = 10.f * db / fmaxf(nq * snB_s, 1e-8f);
    float mx = fmaxf(sf, sb);
    float ef = expf(sf - mx), eb = expf(sb - mx);
    float inv = 1.f / (ef + eb);
    float pfg = ef * inv;
    float pbg = eb * inv;
    float invn = 1.f / fmaxf(nq, 1e-20f);
    g_qn[g] = nq;
    g_invn[g] = invn;
    g_denom[g] = 0.f;

    __shared__ float shv[32];
    __shared__ int   shi[32];
    __shared__ int   swin;
    __shared__ int   wtot[32];
    __shared__ int   wbase[33];

    for (int which = 0; which < 2; which++) {
        float p = which ? pbg : pfg;
        float thres = which ? 0.6f : 0.7f;
        int flag = (p > thres) ? 1 : 0;
        int cnt = __syncthreads_count(flag);
        bool sel;
        if (cnt > 0) {
            sel = (flag != 0);
        } else {
            bool taken = false;
            for (int it = 0; it < TOPK; it++) {
                float v = taken ? -1e30f : p;
                int id = t;
                #pragma unroll
                for (int off = 16; off > 0; off >>= 1) {
                    float ov = __shfl_down_sync(0xffffffffu, v, off);
                    int   oi = __shfl_down_sync(0xffffffffu, id, off);
                    if (ov > v || (ov == v && oi < id)) { v = ov; id = oi; }
                }
                if (lane == 0) { shv[w] = v; shi[w] = id; }
                __syncthreads();
                if (w == 0) {
                    float v2 = shv[lane]; int i2 = shi[lane];
                    #pragma unroll
                    for (int off = 16; off > 0; off >>= 1) {
                        float ov = __shfl_down_sync(0xffffffffu, v2, off);
                        int   oi = __shfl_down_sync(0xffffffffu, i2, off);
                        if (ov > v2 || (ov == v2 && oi < i2)) { v2 = ov; i2 = oi; }
                    }
                    if (lane == 0) swin = i2;
                }
                __syncthreads();
                if (t == swin) taken = true;
            }
            sel = taken;
        }
        float wsum = (cnt > 0) ? (float)cnt : (float)TOPK;
        if (which == 0) {
            g_wf[g] = sel ? 1.f : 0.f;
            if (t == 0) g_wfsum[b] = wsum;
        } else {
            unsigned bal = __ballot_sync(0xffffffffu, sel);
            int wincl = __popc(bal & (0xffffffffu >> (31 - lane)));
            if (lane == 31) wtot[w] = wincl;
            __syncthreads();
            if (w == 0) {
                int tv = wtot[lane];
                int x = tv;
                #pragma unroll
                for (int off = 1; off < 32; off <<= 1) {
                    int y = __shfl_up_sync(0xffffffffu, x, off);
                    if (lane >= off) x += y;
                }
                wbase[lane] = x - tv;
                if (lane == 31) wbase[32] = x;
            }
            __syncthreads();
            if (sel) {
                int pos = wbase[w] + wincl - 1;
                g_idx[b*N + pos]  = t;
                g_invg[b*N + pos] = invn;
            }
            if (t == 0) {
                int M = wbase[32];
                g_M[b] = M;
                g_Mpad[b] = (M + 63) & ~63;
            }
        }
        __syncthreads();
    }
}

// ---------------- K3b: fused fg-proto + gather + bg-proto, 4 rows/block (MLP 4) ----------------
__global__ __launch_bounds__(256) void k_gfg(const float* __restrict__ q) {
    int t = threadIdx.x;
    int j = t & 63;               // lane within row
    int r = t >> 6;               // row within block (0..3)
    int bc = blockIdx.x * 4 + r;
    int b = bc / C;
    int lane = t & 31;
    __shared__ float sh[8];

    const float4* row4 = (const float4*)(q + (size_t)bc*N);
    const float4* wf4  = (const float4*)(g_wf + b*N);
    float s = 0.f;
    #pragma unroll
    for (int i = 0; i < 4; i++) {
        int p = j + i*64;
        float4 v = row4[p], wv = wf4[p];
        s += v.x*wv.x + v.y*wv.y + v.z*wv.z + v.w*wv.w;
    }
    s = warp_sum(s);
    if (lane == 0) sh[t >> 5] = s;
    __syncthreads();
    if (j == 0) g_fgp[bc] = (sh[r*2] + sh[r*2+1]) / g_wfsum[b];

    int Mb = g_M[b], Mpad = g_Mpad[b];
    const int* idx = g_idx + b*N;
    const float* row = q + (size_t)bc*N;
    float* vrow = g_Vg + (size_t)bc*N;
    float sb = 0.f;
    for (int m = j; m < Mb; m += 64) {        // row is L1-hot from the pass above
        float v = row[idx[m]];
        vrow[m] = v;
        sb += v;
    }
    for (int m = Mb + j; m < Mpad; m += 64) vrow[m] = 0.f;
    sb = warp_sum(sb);
    __syncthreads();
    if (lane == 0) sh[t >> 5] = sb;
    __syncthreads();
    if (j == 0) g_bgp[bc] = (sh[r*2] + sh[r*2+1]) / (float)Mb;
}

// ---------------- K5: S = exp(2 cn^T cn), 128(i)x64(m) tiles, double-buffered ----------------
// smem: As[2][32][136] (q tile, k x i), Bs[2][32][72] (Vg tile, k x m) -> 53,248 B dynamic
#define AS5(u,r,c) s5[(size_t)(u)*32*136 + (r)*136 + (c)]
#define BS5(u,r,c) s5[2*32*136 + (size_t)(u)*32*72 + (r)*72 + (c)]
__global__ __launch_bounds__(256) void k5_mma(const float* __restrict__ q) {
    extern __shared__ uint32_t s5[];
    int b  = blockIdx.z;
    int i0 = blockIdx.y * 128;
    int m0 = blockIdx.x * 64;
    int Mb = g_M[b];
    int Mpad = g_Mpad[b];
    if (m0 >= Mpad) return;

    int t = threadIdx.x;
    int lane = t & 31, w = t >> 5;
    int gid = lane >> 2, tig = lane & 3;
    int iw = (w >> 1) * 32;       // 0..96 within 128-i tile
    int mw = (w & 1) * 32;

    float acc[2][4][4] = {};

    const float* qb = q + (size_t)b*C*N;
    const float* vg = g_Vg + (size_t)b*C*N;

    int lrA = t >> 5;             // 0..7
    int lcA = (t & 31) * 4;       // 0..124
    int lrB = t >> 4;             // 0..15
    int lcB = (t & 15) * 4;       // 0..60

    float4 pa[4], pb[2];
    #pragma unroll
    for (int rr = 0; rr < 4; rr++)
        pa[rr] = *(const float4*)(qb + (size_t)(lrA + rr*8)*N + i0 + lcA);
    #pragma unroll
    for (int rr = 0; rr < 2; rr++)
        pb[rr] = *(const float4*)(vg + (size_t)(lrB + rr*16)*N + m0 + lcB);
    #pragma unroll
    for (int rr = 0; rr < 4; rr++) {
        int k = lrA + rr*8;
        AS5(0,k,lcA+0) = f2tf32(pa[rr].x); AS5(0,k,lcA+1) = f2tf32(pa[rr].y);
        AS5(0,k,lcA+2) = f2tf32(pa[rr].z); AS5(0,k,lcA+3) = f2tf32(pa[rr].w);
    }
    #pragma unroll
    for (int rr = 0; rr < 2; rr++) {
        int k = lrB + rr*16;
        BS5(0,k,lcB+0) = f2tf32(pb[rr].x); BS5(0,k,lcB+1) = f2tf32(pb[rr].y);
        BS5(0,k,lcB+2) = f2tf32(pb[rr].z); BS5(0,k,lcB+3) = f2tf32(pb[rr].w);
    }
    __syncthreads();

    for (int c = 0; c < 16; c++) {
        int cur = c & 1, nxt = cur ^ 1;
        if (c + 1 < 16) {
            int k0 = (c + 1) * 32;
            #pragma unroll
            for (int rr = 0; rr < 4; rr++)
                pa[rr] = *(const float4*)(qb + (size_t)(k0 + lrA + rr*8)*N + i0 + lcA);
            #pragma unroll
            for (int rr = 0; rr < 2; rr++)
                pb[rr] = *(const float4*)(vg + (size_t)(k0 + lrB + rr*16)*N + m0 + lcB);
        }
        #pragma unroll
        for (int kk = 0; kk < 32; kk += 8) {
            uint32_t a[2][4];
            #pragma unroll
            for (int ti = 0; ti < 2; ti++) {
                a[ti][0] = AS5(cur, kk + tig    , iw + ti*16 + gid);
                a[ti][1] = AS5(cur, kk + tig    , iw + ti*16 + gid + 8);
                a[ti][2] = AS5(cur, kk + 4 + tig, iw + ti*16 + gid);
                a[ti][3] = AS5(cur, kk + 4 + tig, iw + ti*16 + gid + 8);
            }
            #pragma unroll
            for (int j = 0; j < 4; j++) {
                uint32_t b0 = BS5(cur, kk + tig    , mw + 8*j + gid);
                uint32_t b1 = BS5(cur, kk + 4 + tig, mw + 8*j + gid);
                mma_tf32(acc[0][j], a[0][0], a[0][1], a[0][2], a[0][3], b0, b1);
                mma_tf32(acc[1][j], a[1][0], a[1][1], a[1][2], a[1][3], b0, b1);
            }
        }
        if (c + 1 < 16) {
            #pragma unroll
            for (int rr = 0; rr < 4; rr++) {
                int k = lrA + rr*8;
                AS5(nxt,k,lcA+0) = f2tf32(pa[rr].x); AS5(nxt,k,lcA+1) = f2tf32(pa[rr].y);
                AS5(nxt,k,lcA+2) = f2tf32(pa[rr].z); AS5(nxt,k,lcA+3) = f2tf32(pa[rr].w);
            }
            #pragma unroll
            for (int rr = 0; rr < 2; rr++) {
                int k = lrB + rr*16;
                BS5(nxt,k,lcB+0) = f2tf32(pb[rr].x); BS5(nxt,k,lcB+1) = f2tf32(pb[rr].y);
                BS5(nxt,k,lcB+2) = f2tf32(pb[rr].z); BS5(nxt,k,lcB+3) = f2tf32(pb[rr].w);
            }
            __syncthreads();
        }
    }

    #pragma unroll
    for (int ti = 0; ti < 2; ti++) {
        int ilo = i0 + iw + ti*16 + gid;
        int ihi = ilo + 8;
        float invlo = g_invn[b*N + ilo];
        float invhi = g_invn[b*N + ihi];
        float slo = 0.f, shi2 = 0.f;
        #pragma unroll
        for (int j = 0; j < 4; j++) {
            int m = m0 + mw + 8*j + 2*tig;
            bool in0 = m < Mb, in1 = (m + 1) < Mb;
            float ig0 = in0 ? g_invg[b*N + m]     : 0.f;
            float ig1 = in1 ? g_invg[b*N + m + 1] : 0.f;
            float e00 = in0 ? __expf(2.f * acc[ti][j][0] * invlo * ig0) : 0.f;
            float e01 = in1 ? __expf(2.f * acc[ti][j][1] * invlo * ig1) : 0.f;
            float e10 = in0 ? __expf(2.f * acc[ti][j][2] * invhi * ig0) : 0.f;
            float e11 = in1 ? __expf(2.f * acc[ti][j][3] * invhi * ig1) : 0.f;
            float* r0 = g_S + ((size_t)b*N + ilo)*N + m;
            float* r1 = g_S + ((size_t)b*N + ihi)*N + m;
            r0[0] = e00; r0[1] = e01;
            r1[0] = e10; r1[1] = e11;
            slo  += e00 + e01;
            shi2 += e10 + e11;
        }
        slo  += __shfl_xor_sync(0xffffffffu, slo, 1);
        slo  += __shfl_xor_sync(0xffffffffu, slo, 2);
        shi2 += __shfl_xor_sync(0xffffffffu, shi2, 1);
        shi2 += __shfl_xor_sync(0xffffffffu, shi2, 2);
        if (tig == 0) {
            atomicAdd(&g_denom[b*N + ilo], slo);
            atomicAdd(&g_denom[b*N + ihi], shi2);
        }
    }
}

// ---------------- K7: bg_local GEMM, 128(c)x64(i) tiles, double-buffered + fused epilogue ----------------
// smem: As[2][128][36] (Vg), Bs[2][64][36] (S) -> 55,296 B dynamic; bp tile 128x65 aliased
#define AS7(u,r,c) (((uint32_t*)s7)[(size_t)(u)*128*36 + (r)*36 + (c)])
#define BS7(u,r,c) (((uint32_t*)s7)[2*128*36 + (size_t)(u)*64*36 + (r)*36 + (c)])
#define BP7(r,c)   (s7[(r)*65 + (c)])
__global__ __launch_bounds__(256) void k7_mma(const float* __restrict__ q) {
    extern __shared__ float s7[];
    int b  = blockIdx.z;
    int c0 = blockIdx.y * 128;
    int i0 = blockIdx.x * 64;
    int Mpad = g_Mpad[b];

    int t = threadIdx.x;
    int lane = t & 31, w = t >> 5;
    int gid = lane >> 2, tig = lane & 3;
    int cw = (w >> 1) * 32;       // 0..96 within 128-c tile
    int iw = (w & 1) * 32;

    float acc[2][4][4] = {};

    int lr = t >> 3;              // 0..31
    int lc = (t & 7) * 4;         // 0..28
    int nchunk = Mpad >> 5;

    float4 pa[4], pb[2];
    #pragma unroll
    for (int rr = 0; rr < 4; rr++)
        pa[rr] = *(const float4*)(g_Vg + ((size_t)b*C + c0 + lr + rr*32)*N + lc);
    #pragma unroll
    for (int rr = 0; rr < 2; rr++)
        pb[rr] = *(const float4*)(g_S  + ((size_t)b*N + i0 + lr + rr*32)*N + lc);
    #pragma unroll
    for (int rr = 0; rr < 4; rr++) {
        int r = lr + rr*32;
        AS7(0,r,lc+0) = f2tf32(pa[rr].x); AS7(0,r,lc+1) = f2tf32(pa[rr].y);
        AS7(0,r,lc+2) = f2tf32(pa[rr].z); AS7(0,r,lc+3) = f2tf32(pa[rr].w);
    }
    #pragma unroll
    for (int rr = 0; rr < 2; rr++) {
        int r = lr + rr*32;
        BS7(0,r,lc+0) = f2tf32(pb[rr].x); BS7(0,r,lc+1) = f2tf32(pb[rr].y);
        BS7(0,r,lc+2) = f2tf32(pb[rr].z); BS7(0,r,lc+3) = f2tf32(pb[rr].w);
    }
    __syncthreads();

    for (int c = 0; c < nchunk; c++) {
        int cur = c & 1, nxt = cur ^ 1;
        if (c + 1 < nchunk) {
            int m0 = (c + 1) * 32;
            #pragma unroll
            for (int rr = 0; rr < 4; rr++)
                pa[rr] = *(const float4*)(g_Vg + ((size_t)b*C + c0 + lr + rr*32)*N + m0 + lc);
            #pragma unroll
            for (int rr = 0; rr < 2; rr++)
                pb[rr] = *(const float4*)(g_S  + ((size_t)b*N + i0 + lr + rr*32)*N + m0 + lc);
        }
        #pragma unroll
        for (int kk = 0; kk < 32; kk += 8) {
            uint32_t a[2][4];
            #pragma unroll
            for (int tc = 0; tc < 2; tc++) {
                a[tc][0] = AS7(cur, cw + tc*16 + gid    , kk + tig);
                a[tc][1] = AS7(cur, cw + tc*16 + gid + 8, kk + tig);
                a[tc][2] = AS7(cur, cw + tc*16 + gid    , kk + 4 + tig);
                a[tc][3] = AS7(cur, cw + tc*16 + gid + 8, kk + 4 + tig);
            }
            #pragma unroll
            for (int j = 0; j < 4; j++) {
                uint32_t b0 = BS7(cur, iw + 8*j + gid, kk + tig);
                uint32_t b1 = BS7(cur, iw + 8*j + gid, kk + 4 + tig);
                mma_tf32(acc[0][j], a[0][0], a[0][1], a[0][2], a[0][3], b0, b1);
                mma_tf32(acc[1][j], a[1][0], a[1][1], a[1][2], a[1][3], b0, b1);
            }
        }
        if (c + 1 < nchunk) {
            #pragma unroll
            for (int rr = 0; rr < 4; rr++) {
                int r = lr + rr*32;
                AS7(nxt,r,lc+0) = f2tf32(pa[rr].x); AS7(nxt,r,lc+1) = f2tf32(pa[rr].y);
                AS7(nxt,r,lc+2) = f2tf32(pa[rr].z); AS7(nxt,r,lc+3) = f2tf32(pa[rr].w);
            }
            #pragma unroll
            for (int rr = 0; rr < 2; rr++) {
                int r = lr + rr*32;
                BS7(nxt,r,lc+0) = f2tf32(pb[rr].x); BS7(nxt,r,lc+1) = f2tf32(pb[rr].y);
                BS7(nxt,r,lc+2) = f2tf32(pb[rr].z); BS7(nxt,r,lc+3) = f2tf32(pb[rr].w);
            }
            __syncthreads();
        }
    }
    __syncthreads();   // all frag reads done before bp tile overwrites the alias

    // epilogue: bp tile into smem (bp = 0.3 bgp + 0.7 acc/denom)
    #pragma unroll
    for (int tc = 0; tc < 2; tc++) {
        int clo = c0 + cw + tc*16 + gid;
        float bglo = 0.3f * g_bgp[b*C + clo];
        float bghi = 0.3f * g_bgp[b*C + clo + 8];
        #pragma unroll
        for (int j = 0; j < 4; j++) {
            int i = iw + 8*j + 2*tig;
            float d0 = 0.7f / g_denom[b*N + i0 + i];
            float d1 = 0.7f / g_denom[b*N + i0 + i + 1];
            BP7(cw + tc*16 + gid    , i  ) = bglo + acc[tc][j][0] * d0;
            BP7(cw + tc*16 + gid    , i+1) = bglo + acc[tc][j][1] * d1;
            BP7(cw + tc*16 + gid + 8, i  ) = bghi + acc[tc][j][2] * d0;
            BP7(cw + tc*16 + gid + 8, i+1) = bghi + acc[tc][j][3] * d1;
        }
    }
    __syncthreads();

    // reduction: 4 threads per pixel, 32 channels each, bank-conflict-free via k-rotation
    int px = t >> 2;              // 0..63
    int cs = (t & 3) * 32;        // 0,32,64,96
    int rot = (t & 3) * 8;
    int i = i0 + px;
    const float* qcol = q + ((size_t)b*C + c0 + cs)*N + i;
    const float* fpv  = g_FP  + b*C + c0 + cs;
    const float* fgv  = g_fgp + b*C + c0 + cs;
    float sdf = 0.f, sdb = 0.f, sbb = 0.f;
    #pragma unroll
    for (int k = 0; k < 32; k++) {
        int kr = (k + rot) & 31;
        float qv = qcol[(size_t)kr*N];
        float bp = BP7(cs + kr, px);
        sdf += qv * (0.5f * (fpv[kr] + fgv[kr]));
        sdb += qv * bp;
        sbb += bp * bp;
    }
    sdf += __shfl_xor_sync(0xffffffffu, sdf, 1);
    sdf += __shfl_xor_sync(0xffffffffu, sdf, 2);
    sdb += __shfl_xor_sync(0xffffffffu, sdb, 1);
    sdb += __shfl_xor_sync(0xffffffffu, sdb, 2);
    sbb += __shfl_xor_sync(0xffffffffu, sbb, 1);
    sbb += __shfl_xor_sync(0xffffffffu, sbb, 2);
    if ((t & 3) == 0) {
        int cb = blockIdx.y;
        g_odf[cb][b*N + i] = sdf;
        g_odb[cb][b*N + i] = sdb;
        g_obb[cb][b*N + i] = sbb;
    }
}

// ---------------- K8: inline nFP1 + combine partials + write output ----------------
__global__ void k_out2(float* __restrict__ out) {
    __shared__ float sh[256];
    __shared__ float snF1;
    int t = threadIdx.x;
    int g = blockIdx.x * 256 + t;
    int b = g / N, n = g % N;
    float v0 = 0.5f * (g_FP[b*C + t]       + g_fgp[b*C + t]);
    float v1 = 0.5f * (g_FP[b*C + 256 + t] + g_fgp[b*C + 256 + t]);
    sh[t] = v0*v0 + v1*v1; __syncthreads();
    for (int off = 128; off > 0; off >>= 1) { if (t < off) sh[t] += sh[t+off]; __syncthreads(); }
    if (t == 0) snF1 = sqrtf(sh[0]);
    __syncthreads();

    float df = 0.f, db = 0.f, bb = 0.f;
    #pragma unroll
    for (int k = 0; k < OC; k++) {
        df += g_odf[k][g];
        db += g_odb[k][g];
        bb += g_obb[k][g];
    }
    float nq = g_qn[g];
    float nb = sqrtf(bb);
    out[(b*2 + 0)*N + n] = 10.f * db / fmaxf(nq * nb, 1e-8f);
    out[(b*2 + 1)*N + n] = 10.f * df / fmaxf(nq * snF1, 1e-8f);
}

// ---------------- launch ----------------
extern "C" void kernel_launch(void* const* d_in, const int* in_sizes, int n_in,
                              void* d_out, int out_size) {
    const float* q    = (const float*)d_in[0];
    const float* sf   = (const float*)d_in[1];
    const int*   mask = (const int*)d_in[2];
    float* out = (float*)d_out;

    const int SMEM5 = (2*32*136 + 2*32*72) * 4;   // 53,248 B
    const int SMEM7 = (2*128*36 + 2*64*36) * 4;   // 55,296 B
    cudaFuncSetAttribute(k5_mma, cudaFuncAttributeMaxDynamicSharedMemorySize, SMEM5);
    cudaFuncSetAttribute(k7_mma, cudaFuncAttributeMaxDynamicSharedMemorySize, SMEM7);

    k_pool  <<<B*C/8, 256>>>(sf, mask);
    k_pred1 <<<dim3(B*N/512, NCHP), 256>>>(q);
    k_predw <<<B, 1024>>>();
    k_gfg   <<<B*C/4, 256>>>(q);
    k5_mma  <<<dim3(N/64, N/128, B), 256, SMEM5>>>(q);
    k7_mma  <<<dim3(N/64, C/128, B), 256, SMEM7>>>(q);
    k_out2  <<<B*N/256, 256>>>(out);
}